// round 15
// baseline (speedup 1.0000x reference)
#include <cuda_runtime.h>
#include <cuda_fp16.h>
#include <math.h>
#include <stdint.h>

#define NB 32
#define NC 1536
#define NN 1024
#define NHID 512
#define NL 128
#define NM 64
#define NG 256

#define APAD 40
#define BPAD 136
#define A_BYTES (128 * APAD * 2)
#define B_BYTES (32 * BPAD * 2)
#define STAGE_BYTES (2 * A_BYTES + B_BYTES)
#define SMEM_TOTAL (2 * STAGE_BYTES)        // 58368

// GEMM1 (bz-batched x2) smem
#define G1_A 10240
#define G1_B 8704
#define G1_STAGE (G1_A + 2 * G1_B)          // 27648
#define G1_SMEM (2 * G1_STAGE)              // 55296

// ---- scratch ----
__device__ __half g_x  [(size_t)NB * NC * NN];
__device__ __half g_h  [(size_t)NB * 1024 * NN];
__device__ __half g_f  [(size_t)NB * NL * NN];
__device__ __half g_fnj[(size_t)NB * NN * NL];
__device__ __half g_fnk[(size_t)NB * NL * NN];
__device__ float  g_p  [(size_t)NB * NM * NN];
__device__ __half g_Pt [(size_t)NB * NN * NM];
__device__ __half g_wAh[1024 * NC];
__device__ float  g_bA [1024];
__device__ __half g_wch[NL * NHID];
__device__ __half g_wsh[NM * NHID];
__device__ float g_u[NB * (NM + 1)];
__device__ float g_v[NB * NN];
__device__ float g_bw[NB * NN];
__device__ float g_aggq[4][(size_t)NB * NL * NM];
__device__ float g_tht[NB * NHID];
__device__ float g_tk[NB * NG];

__device__ __forceinline__ uint32_t smem_u32(const void* p) {
    uint32_t a;
    asm("{ .reg .u64 t; cvta.to.shared.u64 t, %1; cvt.u32.u64 %0, t; }" : "=r"(a) : "l"(p));
    return a;
}
__device__ __forceinline__ void cp16(uint32_t d, const void* s, bool pred) {
    int sz = pred ? 16 : 0;
    asm volatile("cp.async.cg.shared.global [%0], [%1], 16, %2;"
                 :: "r"(d), "l"(s), "r"(sz) : "memory");
}
#define CP_COMMIT() asm volatile("cp.async.commit_group;" ::: "memory")
#define CP_WAIT0()  asm volatile("cp.async.wait_group 0;" ::: "memory")

__device__ __forceinline__ void ldmx4(uint32_t* r, uint32_t a) {
    asm volatile("ldmatrix.sync.aligned.m8n8.x4.shared.b16 {%0,%1,%2,%3}, [%4];"
        : "=r"(r[0]), "=r"(r[1]), "=r"(r[2]), "=r"(r[3]) : "r"(a));
}
__device__ __forceinline__ void ldmx2t(uint32_t* r, uint32_t a) {
    asm volatile("ldmatrix.sync.aligned.m8n8.x2.trans.shared.b16 {%0,%1}, [%2];"
        : "=r"(r[0]), "=r"(r[1]) : "r"(a));
}
__device__ __forceinline__ void mma16816(float* d, const uint32_t* a, const uint32_t* b) {
    asm volatile("mma.sync.aligned.m16n8k16.row.col.f32.f16.f16.f32 "
        "{%0,%1,%2,%3}, {%4,%5,%6,%7}, {%8,%9}, {%0,%1,%2,%3};"
        : "+f"(d[0]), "+f"(d[1]), "+f"(d[2]), "+f"(d[3])
        : "r"(a[0]), "r"(a[1]), "r"(a[2]), "r"(a[3]), "r"(b[0]), "r"(b[1]));
}

// ================= generic GEMM tile (validated) =================
template<int MI>
__device__ void gemm_tile(
    int bx, int by, int bz,
    const __half* __restrict__ Ah, const __half* __restrict__ Al, long sA, int ldA,
    const __half* __restrict__ B, long sB,
    int K, int ldB, int Mvalid, int Nvalid,
    const float* __restrict__ bias, int relu, int mode,
    __half* __restrict__ oh, float* __restrict__ of, long sO, int ldo,
    const float* __restrict__ pa, const float* __restrict__ pb)
{
    extern __shared__ char smem[];
    const uint32_t su = smem_u32(smem);
    const int tid = threadIdx.x, lane = tid & 31, wid = tid >> 5;
    const int wm = wid >> 2, wn = wid & 3;
    const int n0 = bx * 128, m0 = by * (MI * 32);
    const bool x2 = (Al != nullptr);

    const __half* A_h = Ah + (long)bz * sA + (long)m0 * ldA;
    const __half* A_l = x2 ? Al + (long)bz * sA + (long)m0 * ldA : A_h;
    const __half* B_p = B + (long)bz * sB;
    const int mMax = (Mvalid - m0 < MI * 32) ? (Mvalid - m0) : MI * 32;

    float acc[MI][4][4];
#pragma unroll
    for (int i = 0; i < MI; i++)
#pragma unroll
        for (int j = 0; j < 4; j++)
#pragma unroll
            for (int q = 0; q < 4; q++) acc[i][j][q] = 0.f;

    const int nc = K >> 5;

    auto prefetch = [&](int c, int st) {
        uint32_t sa = su + st * STAGE_BYTES;
        long kb = (long)c * 32;
#pragma unroll
        for (int i = 0; i < MI / 2; i++) {
            int idx = tid + i * 256;
            int row = idx >> 2, cc = idx & 3;
            uint32_t doff = sa + row * (APAD * 2) + cc * 16;
            bool p = row < mMax;
            cp16(doff, A_h + (long)row * ldA + kb + cc * 8, p);
            if (x2) cp16(doff + A_BYTES, A_l + (long)row * ldA + kb + cc * 8, p);
        }
#pragma unroll
        for (int i = 0; i < 2; i++) {
            int idx = tid + i * 256;
            int row = idx >> 4, cc = idx & 15;
            uint32_t doff = sa + 2 * A_BYTES + row * (BPAD * 2) + cc * 16;
            bool p = (n0 + cc * 8) < Nvalid;
            cp16(doff, B_p + (kb + row) * (long)ldB + n0 + cc * 8, p);
        }
    };

    prefetch(0, 0);
    CP_COMMIT();

    for (int c = 0; c < nc; c++) {
        CP_WAIT0();
        __syncthreads();
        if (c + 1 < nc) { prefetch(c + 1, (c + 1) & 1); CP_COMMIT(); }

        uint32_t sa = su + (c & 1) * STAGE_BYTES;
#pragma unroll
        for (int kk = 0; kk < 2; kk++) {
            uint32_t afh[MI][4], afl[MI][4];
#pragma unroll
            for (int mi = 0; mi < MI; mi++) {
                uint32_t ad = sa + ((wm * (MI * 16) + mi * 16 + (lane & 15)) * APAD
                                    + kk * 16 + (lane >> 4) * 8) * 2;
                ldmx4(afh[mi], ad);
                if (x2) ldmx4(afl[mi], ad + A_BYTES);
            }
            uint32_t bf[4][2];
#pragma unroll
            for (int ni = 0; ni < 4; ni++) {
                uint32_t bd = sa + 2 * A_BYTES
                            + (kk * 16 + (lane & 15)) * (BPAD * 2)
                            + (wn * 32 + ni * 8) * 2;
                ldmx2t(bf[ni], bd);
            }
#pragma unroll
            for (int ni = 0; ni < 4; ni++)
#pragma unroll
                for (int mi = 0; mi < MI; mi++)
                    mma16816(acc[mi][ni], afh[mi], bf[ni]);
            if (x2) {
#pragma unroll
                for (int ni = 0; ni < 4; ni++)
#pragma unroll
                    for (int mi = 0; mi < MI; mi++)
                        mma16816(acc[mi][ni], afl[mi], bf[ni]);
            }
        }
    }

    const int g = lane >> 2, tq = lane & 3;
    if (mode >= 2) {
        const float a = *pa, bb = *pb;
        const bool fast = (fabsf(a) + fabsf(bb)) <= 1.0f;
        float csum[4][2];
#pragma unroll
        for (int ni = 0; ni < 4; ni++) { csum[ni][0] = 0.f; csum[ni][1] = 0.f; }
#pragma unroll
        for (int mi = 0; mi < MI; mi++) {
            float r0 = 0.f, r1 = 0.f;
#pragma unroll
            for (int ni = 0; ni < 4; ni++) {
#pragma unroll
                for (int q = 0; q < 4; q++) {
                    float z = a * acc[mi][ni][q] + bb;
                    float s;
                    if (fast) {
                        float tt = 0.5f * z, t2 = tt * tt;
                        float th = tt * (1.f + t2 * (-0.3333333333f
                                   + t2 * (0.1333333333f - t2 * 0.05396825397f)));
                        s = 0.5f + 0.5f * th;
                    } else {
                        s = 1.f / (1.f + __expf(-z));
                    }
                    if (q < 2) r0 += s; else r1 += s;
                    csum[ni][q & 1] += s;
                }
            }
            r0 += __shfl_xor_sync(0xffffffffu, r0, 1);
            r0 += __shfl_xor_sync(0xffffffffu, r0, 2);
            r1 += __shfl_xor_sync(0xffffffffu, r1, 1);
            r1 += __shfl_xor_sync(0xffffffffu, r1, 2);
            if (tq == 0) {
                int j = m0 + wm * (MI * 16) + mi * 16 + g;
                atomicAdd(&g_bw[bz * NN + j], r0);
                atomicAdd(&g_bw[bz * NN + j + 8], r1);
            }
        }
        if (mode == 3) {
#pragma unroll
            for (int ni = 0; ni < 4; ni++) {
                float c0 = csum[ni][0], c1 = csum[ni][1];
#pragma unroll
                for (int off = 4; off < 32; off <<= 1) {
                    c0 += __shfl_xor_sync(0xffffffffu, c0, off);
                    c1 += __shfl_xor_sync(0xffffffffu, c1, off);
                }
                if (lane < 4) {
                    int col = n0 + wn * 32 + ni * 8 + lane * 2;
                    atomicAdd(&g_bw[bz * NN + col], c0);
                    atomicAdd(&g_bw[bz * NN + col + 1], c1);
                }
            }
        }
        return;
    }

#pragma unroll
    for (int mi = 0; mi < MI; mi++) {
        int r0 = m0 + wm * (MI * 16) + mi * 16 + g;
        int r1 = r0 + 8;
        float b0v = (bias && r0 < Mvalid) ? bias[r0] : 0.f;
        float b1v = (bias && r1 < Mvalid) ? bias[r1] : 0.f;
#pragma unroll
        for (int ni = 0; ni < 4; ni++) {
            int col = n0 + wn * 32 + ni * 8 + tq * 2;
            if (col >= Nvalid) continue;
            float v00 = acc[mi][ni][0] + b0v, v01 = acc[mi][ni][1] + b0v;
            float v10 = acc[mi][ni][2] + b1v, v11 = acc[mi][ni][3] + b1v;
            if (relu) {
                v00 = fmaxf(v00, 0.f); v01 = fmaxf(v01, 0.f);
                v10 = fmaxf(v10, 0.f); v11 = fmaxf(v11, 0.f);
            }
            if (mode == 0) {
                if (r0 < Mvalid) {
                    long off = (long)bz * sO + (long)r0 * ldo + col;
                    __half h0 = __float2half_rn(v00), h1 = __float2half_rn(v01);
                    *reinterpret_cast<uint32_t*>(oh + off) =
                        (uint32_t)__half_as_ushort(h0) | ((uint32_t)__half_as_ushort(h1) << 16);
                }
                if (r1 < Mvalid) {
                    long off = (long)bz * sO + (long)r1 * ldo + col;
                    __half h0 = __float2half_rn(v10), h1 = __float2half_rn(v11);
                    *reinterpret_cast<uint32_t*>(oh + off) =
                        (uint32_t)__half_as_ushort(h0) | ((uint32_t)__half_as_ushort(h1) << 16);
                }
            } else {
                if (r0 < Mvalid)
                    *reinterpret_cast<float2*>(of + (long)bz * sO + (long)r0 * ldo + col) =
                        make_float2(v00, v01);
                if (r1 < Mvalid)
                    *reinterpret_cast<float2*>(of + (long)bz * sO + (long)r1 * ldo + col) =
                        make_float2(v10, v11);
            }
        }
    }
}

// ================= GEMM1: 2 batches per CTA (A smem shared) =================
__device__ void gemm1_body(int bx, int by, int bzp)
{
    extern __shared__ char smem[];
    const uint32_t su = smem_u32(smem);
    const int tid = threadIdx.x, lane = tid & 31, wid = tid >> 5;
    const int wm = wid >> 2, wn = wid & 3;
    const int n0 = bx * 128, m0 = by * 128;
    const int bz0 = bzp * 2;

    const __half* A_h = g_wAh + (long)m0 * NC;
    const __half* B0 = g_x + (long)bz0 * NC * NN;
    const __half* B1 = B0 + (long)NC * NN;

    float acc0[4][4][4], acc1[4][4][4];
#pragma unroll
    for (int i = 0; i < 4; i++)
#pragma unroll
        for (int j = 0; j < 4; j++)
#pragma unroll
            for (int q = 0; q < 4; q++) { acc0[i][j][q] = 0.f; acc1[i][j][q] = 0.f; }

    const int nc = NC >> 5;   // 48

    auto prefetch = [&](int c, int st) {
        uint32_t sa = su + st * G1_STAGE;
        long kb = (long)c * 32;
#pragma unroll
        for (int i = 0; i < 2; i++) {
            int idx = tid + i * 256;
            int row = idx >> 2, cc = idx & 3;
            cp16(sa + row * (APAD * 2) + cc * 16, A_h + (long)row * NC + kb + cc * 8, true);
        }
#pragma unroll
        for (int i = 0; i < 2; i++) {
            int idx = tid + i * 256;
            int row = idx >> 4, cc = idx & 15;
            uint32_t doff = sa + G1_A + row * (BPAD * 2) + cc * 16;
            const long goff = (kb + row) * (long)NN + n0 + cc * 8;
            cp16(doff, B0 + goff, true);
            cp16(doff + G1_B, B1 + goff, true);
        }
    };

    prefetch(0, 0);
    CP_COMMIT();

    for (int c = 0; c < nc; c++) {
        CP_WAIT0();
        __syncthreads();
        if (c + 1 < nc) { prefetch(c + 1, (c + 1) & 1); CP_COMMIT(); }

        uint32_t sa = su + (c & 1) * G1_STAGE;
#pragma unroll
        for (int kk = 0; kk < 2; kk++) {
            uint32_t afh[4][4];
#pragma unroll
            for (int mi = 0; mi < 4; mi++) {
                uint32_t ad = sa + ((wm * 64 + mi * 16 + (lane & 15)) * APAD
                                    + kk * 16 + (lane >> 4) * 8) * 2;
                ldmx4(afh[mi], ad);
            }
#pragma unroll
            for (int ni = 0; ni < 4; ni++) {
                uint32_t bd = sa + G1_A
                            + (kk * 16 + (lane & 15)) * (BPAD * 2)
                            + (wn * 32 + ni * 8) * 2;
                uint32_t bf0[2], bf1[2];
                ldmx2t(bf0, bd);
                ldmx2t(bf1, bd + G1_B);
#pragma unroll
                for (int mi = 0; mi < 4; mi++) {
                    mma16816(acc0[mi][ni], afh[mi], bf0);
                    mma16816(acc1[mi][ni], afh[mi], bf1);
                }
            }
        }
    }

    const int g = lane >> 2, tq = lane & 3;
#pragma unroll
    for (int mi = 0; mi < 4; mi++) {
        int r0 = m0 + wm * 64 + mi * 16 + g;
        int r1 = r0 + 8;
        float b0v = g_bA[r0], b1v = g_bA[r1];
#pragma unroll
        for (int ni = 0; ni < 4; ni++) {
            int col = n0 + wn * 32 + ni * 8 + tq * 2;
#pragma unroll
            for (int bb = 0; bb < 2; bb++) {
                float (*ac)[4][4] = bb ? acc1 : acc0;
                long base = ((long)(bz0 + bb) * 1024);
                float v00 = fmaxf(ac[mi][ni][0] + b0v, 0.f);
                float v01 = fmaxf(ac[mi][ni][1] + b0v, 0.f);
                float v10 = fmaxf(ac[mi][ni][2] + b1v, 0.f);
                float v11 = fmaxf(ac[mi][ni][3] + b1v, 0.f);
                __half h0 = __float2half_rn(v00), h1 = __float2half_rn(v01);
                *reinterpret_cast<uint32_t*>(g_h + (base + r0) * NN + col) =
                    (uint32_t)__half_as_ushort(h0) | ((uint32_t)__half_as_ushort(h1) << 16);
                __half h2 = __float2half_rn(v10), h3 = __float2half_rn(v11);
                *reinterpret_cast<uint32_t*>(g_h + (base + r1) * NN + col) =
                    (uint32_t)__half_as_ushort(h2) | ((uint32_t)__half_as_ushort(h3) << 16);
            }
        }
    }
}

// ================= small device bodies =================
__device__ void tk1_body(int bid, const float* __restrict__ t,
                         const float* __restrict__ W, const float* __restrict__ bias)
{
    int gw = (bid * 256 + threadIdx.x) >> 5;
    int lane = threadIdx.x & 31;
    int o = gw % NHID, b = gw / NHID;
    const float* tr = t + (long)b * NC;
    const float* wr = W + (long)o * NC;
    float s = 0.f;
    for (int k = lane; k < NC; k += 32) s = fmaf(tr[k], wr[k], s);
#pragma unroll
    for (int off = 16; off > 0; off >>= 1) s += __shfl_xor_sync(0xffffffffu, s, off);
    if (lane == 0) g_tht[b * NHID + o] = fmaxf(s + bias[o], 0.f);
}
__device__ void tk2_body(int bid, const float* __restrict__ W, const float* __restrict__ bias)
{
    int gw = (bid * 256 + threadIdx.x) >> 5;
    int lane = threadIdx.x & 31;
    int o = gw % NG, b = gw / NG;
    const float* hr = g_tht + (long)b * NHID;
    const float* wr = W + (long)o * NHID;
    float s = 0.f;
    for (int k = lane; k < NHID; k += 32) s = fmaf(hr[k], wr[k], s);
#pragma unroll
    for (int off = 16; off > 0; off >>= 1) s += __shfl_xor_sync(0xffffffffu, s, off);
    if (lane == 0) g_tk[b * NG + o] = s + bias[o];
}
// u-update reading v (iterations 2,3)
__device__ void sk_u_body(int bid, const float* __restrict__ pdust)
{
    const float NORMC = -logf((float)(NM + NN));
    const float LOGN = logf((float)NN);
    int gw = (bid * 256 + threadIdx.x) >> 5;
    int lane = threadIdx.x & 31;
    int i = gw % (NM + 1), b = gw / (NM + 1);

    const float4* v4 = reinterpret_cast<const float4*>(g_v + b * NN);
    float xs[32];
    if (i < NM) {
        const float4* p4 = reinterpret_cast<const float4*>(g_p + ((long)b * NM + i) * NN);
#pragma unroll
        for (int w = 0; w < 8; w++) {
            float4 pv = p4[w * 32 + lane];
            float4 vv = __ldcg(v4 + w * 32 + lane);
            xs[4*w]   = pv.x + vv.x; xs[4*w+1] = pv.y + vv.y;
            xs[4*w+2] = pv.z + vv.z; xs[4*w+3] = pv.w + vv.w;
        }
    } else {
        float dust = *pdust;
#pragma unroll
        for (int w = 0; w < 8; w++) {
            float4 vv = __ldcg(v4 + w * 32 + lane);
            xs[4*w]   = dust + vv.x; xs[4*w+1] = dust + vv.y;
            xs[4*w+2] = dust + vv.z; xs[4*w+3] = dust + vv.w;
        }
    }
    float mx = xs[0];
#pragma unroll
    for (int q = 1; q < 32; q++) mx = fmaxf(mx, xs[q]);
#pragma unroll
    for (int off = 16; off > 0; off >>= 1) mx = fmaxf(mx, __shfl_xor_sync(0xffffffffu, mx, off));
    float s = 0.f;
#pragma unroll
    for (int q = 0; q < 32; q++) s += __expf(xs[q] - mx);
#pragma unroll
    for (int off = 16; off > 0; off >>= 1) s += __shfl_xor_sync(0xffffffffu, s, off);
    if (lane == 0)
        g_u[b * (NM + 1) + i] = ((i < NM) ? NORMC : (LOGN + NORMC)) - (mx + __logf(s));
}
// first u-update: v == 0, no v read
__device__ void sk_u1_body(int bid, const float* __restrict__ pdust)
{
    const float NORMC = -logf((float)(NM + NN));
    const float LOGN = logf((float)NN);
    int gw = (bid * 256 + threadIdx.x) >> 5;
    int lane = threadIdx.x & 31;
    int i = gw % (NM + 1), b = gw / (NM + 1);

    if (i == NM) {
        if (lane == 0)
            g_u[b * (NM + 1) + NM] = LOGN + NORMC - (*pdust + logf((float)NN));
        return;
    }
    const float4* p4 = reinterpret_cast<const float4*>(g_p + ((long)b * NM + i) * NN);
    float xs[32];
#pragma unroll
    for (int w = 0; w < 8; w++) {
        float4 pv = p4[w * 32 + lane];
        xs[4*w] = pv.x; xs[4*w+1] = pv.y; xs[4*w+2] = pv.z; xs[4*w+3] = pv.w;
    }
    float mx = xs[0];
#pragma unroll
    for (int q = 1; q < 32; q++) mx = fmaxf(mx, xs[q]);
#pragma unroll
    for (int off = 16; off > 0; off >>= 1) mx = fmaxf(mx, __shfl_xor_sync(0xffffffffu, mx, off));
    float s = 0.f;
#pragma unroll
    for (int q = 0; q < 32; q++) s += __expf(xs[q] - mx);
#pragma unroll
    for (int off = 16; off > 0; off >>= 1) s += __shfl_xor_sync(0xffffffffu, s, off);
    if (lane == 0)
        g_u[b * (NM + 1) + i] = NORMC - (mx + __logf(s));
}
__device__ void sk_v_body(int bid, const float* __restrict__ pdust)
{
    const float NORMC = -logf((float)(NM + NN));
    __shared__ float su[NM + 1];
    int b = bid >> 2, q = bid & 3;
    int tid = threadIdx.x;
    if (tid <= NM) su[tid] = __ldcg(&g_u[b * (NM + 1) + tid]);
    __syncthreads();
    int j = q * 256 + tid;
    const float* pb = g_p + (long)b * NM * NN + j;
    float mx = *pdust + su[NM];
    float s = 1.f;
#pragma unroll 8
    for (int i = 0; i < NM; i++) {
        float x = pb[(long)i * NN] + su[i];
        if (x > mx) { s = s * __expf(mx - x) + 1.f; mx = x; }
        else        { s += __expf(x - mx); }
    }
    g_v[b * NN + j] = NORMC - (mx + __logf(s));
    __syncthreads();
}
__device__ void convw_body(int bid, int nblk, const float* __restrict__ s,
                           __half* __restrict__ dh, int count)
{
    for (int i = bid * 256 + threadIdx.x; i < count; i += nblk * 256)
        dh[i] = __float2half_rn(s[i]);
}

// ================= merged global kernels =================
__global__ void mega_convert(const float* __restrict__ x,
                             const float* __restrict__ Wc1, const float* __restrict__ Ws1,
                             const float* __restrict__ Wc2, const float* __restrict__ Ws2,
                             const float* __restrict__ bc1, const float* __restrict__ bs1)
{
    int id = blockIdx.x;
    if (id < 4096) {
        long i = (long)id * 256 + threadIdx.x;
        const long total = (long)NB * NC * NN / 4;
        for (; i < total; i += 4096L * 256) {
            float4 v = reinterpret_cast<const float4*>(x)[i];
            __half2 a = __floats2half2_rn(v.x, v.y);
            __half2 b = __floats2half2_rn(v.z, v.w);
            reinterpret_cast<uint2*>(g_x)[i] =
                make_uint2(*reinterpret_cast<uint32_t*>(&a), *reinterpret_cast<uint32_t*>(&b));
        }
    } else if (id < 4224) {
        convw_body(id - 4096, 128, Wc1, g_wAh, NHID * NC);
    } else if (id < 4352) {
        convw_body(id - 4224, 128, Ws1, g_wAh + (size_t)NHID * NC, NHID * NC);
    } else if (id < 4384) {
        convw_body(id - 4352, 32, Wc2, g_wch, NL * NHID);
    } else if (id < 4400) {
        convw_body(id - 4384, 16, Ws2, g_wsh, NM * NHID);
    } else {
        for (int i = threadIdx.x; i < NHID; i += 256) {
            g_bA[i] = bc1[i];
            g_bA[NHID + i] = bs1[i];
        }
    }
}

__global__ void __launch_bounds__(256, 1) k_gemm1(
    const float* __restrict__ t, const float* __restrict__ Wt1, const float* __restrict__ bt1)
{
    int id = blockIdx.x;
    if (id < 1024) {
        gemm1_body(id & 7, (id >> 3) & 7, id >> 6);
    } else {
        tk1_body(id - 1024, t, Wt1, bt1);
    }
}

__global__ void __launch_bounds__(256, 2) k_gemm2(
    const float* __restrict__ bc2, const float* __restrict__ bs2,
    const float* __restrict__ Wt2, const float* __restrict__ bt2)
{
    int id = blockIdx.x;
    if (id < 256) {
        gemm_tile<4>(id & 7, 0, id >> 3,
                     g_wch, nullptr, 0, NHID, g_h, (long)1024 * NN,
                     NHID, NN, NL, NN, bc2, 0, 0,
                     g_f, nullptr, (long)NL * NN, NN, nullptr, nullptr);
    } else if (id < 512) {
        int q = id - 256;
        gemm_tile<2>(q & 7, 0, q >> 3,
                     g_wsh, nullptr, 0, NHID, g_h + (long)NHID * NN, (long)1024 * NN,
                     NHID, NN, NM, NN, bs2, 0, 1,
                     nullptr, g_p, (long)NM * NN, NN, nullptr, nullptr);
    } else {
        tk2_body(id - 512, Wt2, bt2);
    }
}

// fnt + colnorm fused; plus zero(bw) and first Sinkhorn u-update (v==0)
__global__ void fnt2_kernel(const float* __restrict__ pdust)
{
    int id = blockIdx.x;
    if (id < 1024) {
        __shared__ float sf[128][33];
        __shared__ float part[8][32];
        __shared__ float nrm[32];
        int b = id >> 5, n0 = (id & 31) * 32;
        int tx = threadIdx.x & 31, ty = threadIdx.x >> 5;
        long fb = (long)b * NL * NN;
#pragma unroll
        for (int i = 0; i < 16; i++) {
            int l = ty + i * 8;
            sf[l][tx] = __half2float(g_f[fb + (long)l * NN + n0 + tx]);
        }
        __syncthreads();
        float s = 0.f;
#pragma unroll
        for (int i = 0; i < 16; i++) { float v2 = sf[ty * 16 + i][tx]; s = fmaf(v2, v2, s); }
        part[ty][tx] = s;
        __syncthreads();
        if (ty == 0) {
            float tot = 0.f;
#pragma unroll
            for (int i = 0; i < 8; i++) tot += part[i][tx];
            nrm[tx] = fmaxf(sqrtf(tot), 1e-12f);
        }
        __syncthreads();
#pragma unroll
        for (int i = 0; i < 16; i++) {
            int l = ty + i * 8;
            g_fnk[fb + (long)l * NN + n0 + tx] = __float2half_rn(sf[l][tx] / nrm[tx]);
        }
        int l = tx + (ty & 3) * 32;
        int rh = ty >> 2;
#pragma unroll
        for (int i = 0; i < 16; i++) {
            int r = rh * 16 + i;
            g_fnj[((long)b * NN + n0 + r) * NL + l] = __float2half_rn(sf[l][r] / nrm[r]);
        }
    } else if (id < 1152) {
        g_bw[(id - 1024) * 256 + threadIdx.x] = 0.f;
    } else {
        sk_u1_body(id - 1152, pdust);
    }
}

// Sinkhorn stage + slice of symmetric burst Gram
__global__ void __launch_bounds__(256, 2) k_burst_sk(
    int sliceStart, int skN, int phase,
    const float* __restrict__ pdust,
    const float* __restrict__ pa, const float* __restrict__ pb)
{
    int id = blockIdx.x;
    if (id < skN) {
        if (phase == 0) sk_u_body(id, pdust);
        else            sk_v_body(id, pdust);
        return;
    }
    int flat = sliceStart + (id - skN);      // 0..1151
    int bz = flat / 36;
    int rem = flat % 36;
    int jb = 0;
    while (rem >= 8 - jb) { rem -= 8 - jb; jb++; }
    int kb = jb + rem;
    gemm_tile<4>(kb, jb, bz,
                 g_fnj, nullptr, (long)NN * NL, NL, g_fnk, (long)NL * NN,
                 NL, NN, NN, NN, nullptr, 0, (jb == kb) ? 2 : 3,
                 nullptr, nullptr, 0, 0, pa, pb);
}

// transposed P finalize: thread-per-column, cterm folded, coalesced 128B stores
__global__ void pfinal2_kernel(const float* __restrict__ pbp)
{
    const float NORMC = -logf((float)(NM + NN));
    __shared__ float su[NM + 1];
    int b = blockIdx.x >> 2, q = blockIdx.x & 3;
    int tid = threadIdx.x;
    if (tid <= NM) su[tid] = g_u[b * (NM + 1) + tid];
    __syncthreads();
    int j = q * 256 + tid;
    float cv = g_v[b * NN + j] - NORMC - (*pbp) * __logf(g_bw[b * NN + j]);
    const float* pb2 = g_p + (long)b * NM * NN + j;
    uint32_t w[32];
#pragma unroll
    for (int i = 0; i < NM; i += 2) {
        float v0 = __expf(pb2[(long)i * NN] + su[i] + cv);
        float v1 = __expf(pb2[(long)(i + 1) * NN] + su[i + 1] + cv);
        __half2 hh = __floats2half2_rn(v0, v1);
        w[i >> 1] = *reinterpret_cast<uint32_t*>(&hh);
    }
    uint4* dst = reinterpret_cast<uint4*>(g_Pt + ((long)b * NN + j) * NM);
#pragma unroll
    for (int k = 0; k < 8; k++)
        dst[k] = make_uint4(w[4 * k], w[4 * k + 1], w[4 * k + 2], w[4 * k + 3]);
}

// agg split-K x4
__global__ void __launch_bounds__(256, 2) k_agg()
{
    int bz = blockIdx.x & 31, quar = blockIdx.x >> 5;
    gemm_tile<4>(0, 0, bz,
                 g_f + quar * 256, nullptr, (long)NL * NN, NN,
                 g_Pt + (long)quar * 256 * NM, (long)NN * NM,
                 256, NM, NL, NM, nullptr, 0, 1,
                 nullptr, g_aggq[quar], (long)NL * NM, NM, nullptr, nullptr);
}

__global__ void final_kernel(float* __restrict__ out)
{
    const int b = blockIdx.x, tid = threadIdx.x;
    __shared__ float sred[256];
    __shared__ float cnorm[NM];
    __shared__ float stk, stot;

    float v = g_tk[b * NG + tid];
    sred[tid] = v * v;
    __syncthreads();
    for (int s = 128; s > 0; s >>= 1) { if (tid < s) sred[tid] += sred[tid + s]; __syncthreads(); }
    if (tid == 0) stk = fmaxf(sqrtf(sred[0]), 1e-12f);
    __syncthreads();
    {
        int m = tid & 63, part = tid >> 6;
        long ab = (long)b * NL * NM;
        float s = 0.f;
        for (int l = part * 32; l < part * 32 + 32; l++) {
            long o = ab + (long)l * NM + m;
            float x = g_aggq[0][o] + g_aggq[1][o] + g_aggq[2][o] + g_aggq[3][o];
            s = fmaf(x, x, s);
        }
        sred[tid] = s;
        __syncthreads();
        if (tid < 64)
            cnorm[tid] = fmaxf(sqrtf(sred[tid] + sred[tid+64] + sred[tid+128] + sred[tid+192]), 1e-12f);
        __syncthreads();
    }
    const int ROW = NG + NL * NM;
    float* orow = out + (long)b * ROW;
    float tot = 0.f;
    for (int idx = tid; idx < ROW; idx += 256) {
        float val;
        if (idx < NG) val = g_tk[b * NG + idx] / stk;
        else {
            int r = idx - NG;
            long o = ((long)b * NL + (r >> 6)) * NM + (r & 63);
            val = (g_aggq[0][o] + g_aggq[1][o] + g_aggq[2][o] + g_aggq[3][o]) / cnorm[r & 63];
        }
        orow[idx] = val;
        tot += val * val;
    }
    sred[tid] = tot;
    __syncthreads();
    for (int s = 128; s > 0; s >>= 1) { if (tid < s) sred[tid] += sred[tid + s]; __syncthreads(); }
    if (tid == 0) stot = fmaxf(sqrtf(sred[0]), 1e-12f);
    __syncthreads();
    for (int idx = tid; idx < ROW; idx += 256) orow[idx] /= stot;
}

// ============ launcher ============
extern "C" void kernel_launch(void* const* d_in, const int* in_sizes, int n_in,
                              void* d_out, int out_size)
{
    (void)in_sizes; (void)n_in; (void)out_size;
    const float* x    = (const float*)d_in[0];
    const float* t    = (const float*)d_in[1];
    const float* Wc1  = (const float*)d_in[2];
    const float* bc1  = (const float*)d_in[3];
    const float* Wc2  = (const float*)d_in[4];
    const float* bc2  = (const float*)d_in[5];
    const float* Ws1  = (const float*)d_in[6];
    const float* bs1  = (const float*)d_in[7];
    const float* Ws2  = (const float*)d_in[8];
    const float* bs2  = (const float*)d_in[9];
    const float* Wt1  = (const float*)d_in[10];
    const float* bt1  = (const float*)d_in[11];
    const float* Wt2  = (const float*)d_in[12];
    const float* bt2  = (const float*)d_in[13];
    const float* dust = (const float*)d_in[14];
    const float* ba   = (const float*)d_in[15];
    const float* bbp  = (const float*)d_in[16];
    const float* bp   = (const float*)d_in[17];
    float* out = (float*)d_out;

    cudaFuncSetAttribute(k_gemm1,    cudaFuncAttributeMaxDynamicSharedMemorySize, G1_SMEM);
    cudaFuncSetAttribute(k_gemm2,    cudaFuncAttributeMaxDynamicSharedMemorySize, SMEM_TOTAL);
    cudaFuncSetAttribute(k_burst_sk, cudaFuncAttributeMaxDynamicSharedMemorySize, SMEM_TOTAL);
    cudaFuncSetAttribute(k_agg,      cudaFuncAttributeMaxDynamicSharedMemorySize, SMEM_TOTAL);

    // 1: all conversions (incl. x) + bias concat
    mega_convert<<<4401, 256>>>(x, Wc1, Ws1, Wc2, Ws2, bc1, bs1);

    // 2: GEMM1 (2 batches per CTA, A-smem shared) + token MLP layer 1
    k_gemm1<<<3072, 256, G1_SMEM>>>(t, Wt1, bt1);

    // 3: GEMM2c + GEMM2s + token MLP layer 2
    k_gemm2<<<1536, 256, SMEM_TOTAL>>>(bc2, bs2, Wt2, bt2);

    // 4: fnt+colnorm + zero(bw) + Sinkhorn u1 (v==0)
    fnt2_kernel<<<1412, 256>>>(dust);

    // 5-9: burst Gram slices overlapped with remaining Sinkhorn stages (v1,u2,v2,u3,v3)
    {
        int start = 0;
        k_burst_sk<<<128 + 360, 256, SMEM_TOTAL>>>(start, 128, 1, dust, ba, bbp); start += 360;
        k_burst_sk<<<260 + 36,  256, SMEM_TOTAL>>>(start, 260, 0, dust, ba, bbp); start += 36;
        k_burst_sk<<<128 + 360, 256, SMEM_TOTAL>>>(start, 128, 1, dust, ba, bbp); start += 360;
        k_burst_sk<<<260 + 36,  256, SMEM_TOTAL>>>(start, 260, 0, dust, ba, bbp); start += 36;
        k_burst_sk<<<128 + 360, 256, SMEM_TOTAL>>>(start, 128, 1, dust, ba, bbp);
    }

    // 10: transport plan (transposed, cterm folded)
    pfinal2_kernel<<<128, 256>>>(bp);

    // 11-12: aggregation (split-K x4) + final normalize
    k_agg<<<128, 256, SMEM_TOTAL>>>();
    final_kernel<<<NB, 256>>>(out);
}

// round 16
// speedup vs baseline: 1.0425x; 1.0425x over previous
#include <cuda_runtime.h>
#include <cuda_fp16.h>
#include <math.h>
#include <stdint.h>

#define NB 32
#define NC 1536
#define NN 1024
#define NHID 512
#define NL 128
#define NM 64
#define NG 256

#define APAD 40
#define BPAD 136
#define A_BYTES (128 * APAD * 2)
#define B_BYTES (32 * BPAD * 2)
#define STAGE_BYTES (2 * A_BYTES + B_BYTES)
#define SMEM_TOTAL (2 * STAGE_BYTES)        // 58368

// ---- scratch ----
__device__ __half g_h  [(size_t)NB * 1024 * NN];
__device__ __half g_f  [(size_t)NB * NL * NN];
__device__ __half g_fnj[(size_t)NB * NN * NL];
__device__ __half g_fnk[(size_t)NB * NL * NN];
__device__ float  g_p  [(size_t)NB * NM * NN];
__device__ __half g_Pt [(size_t)NB * NN * NM];
__device__ __half g_wAh[1024 * NC];
__device__ float  g_bA [1024];
__device__ __half g_wch[NL * NHID];
__device__ __half g_wsh[NM * NHID];
__device__ float g_u[NB * (NM + 1)];
__device__ float g_v[NB * NN];
__device__ float g_bw[NB * NN];
__device__ float g_aggq[4][(size_t)NB * NL * NM];
__device__ float g_tht[NB * NHID];
__device__ float g_tk[NB * NG];

__device__ __forceinline__ uint32_t smem_u32(const void* p) {
    uint32_t a;
    asm("{ .reg .u64 t; cvta.to.shared.u64 t, %1; cvt.u32.u64 %0, t; }" : "=r"(a) : "l"(p));
    return a;
}
__device__ __forceinline__ void cp16(uint32_t d, const void* s, bool pred) {
    int sz = pred ? 16 : 0;
    asm volatile("cp.async.cg.shared.global [%0], [%1], 16, %2;"
                 :: "r"(d), "l"(s), "r"(sz) : "memory");
}
#define CP_COMMIT() asm volatile("cp.async.commit_group;" ::: "memory")
#define CP_WAIT0()  asm volatile("cp.async.wait_group 0;" ::: "memory")

__device__ __forceinline__ void ldmx4(uint32_t* r, uint32_t a) {
    asm volatile("ldmatrix.sync.aligned.m8n8.x4.shared.b16 {%0,%1,%2,%3}, [%4];"
        : "=r"(r[0]), "=r"(r[1]), "=r"(r[2]), "=r"(r[3]) : "r"(a));
}
__device__ __forceinline__ void ldmx2t(uint32_t* r, uint32_t a) {
    asm volatile("ldmatrix.sync.aligned.m8n8.x2.trans.shared.b16 {%0,%1}, [%2];"
        : "=r"(r[0]), "=r"(r[1]) : "r"(a));
}
__device__ __forceinline__ void mma16816(float* d, const uint32_t* a, const uint32_t* b) {
    asm volatile("mma.sync.aligned.m16n8k16.row.col.f32.f16.f16.f32 "
        "{%0,%1,%2,%3}, {%4,%5,%6,%7}, {%8,%9}, {%0,%1,%2,%3};"
        : "+f"(d[0]), "+f"(d[1]), "+f"(d[2]), "+f"(d[3])
        : "r"(a[0]), "r"(a[1]), "r"(a[2]), "r"(a[3]), "r"(b[0]), "r"(b[1]));
}

// ================= generic GEMM tile (validated) =================
template<int MI>
__device__ void gemm_tile(
    int bx, int by, int bz,
    const __half* __restrict__ Ah, const __half* __restrict__ Al, long sA, int ldA,
    const __half* __restrict__ B, long sB,
    int K, int ldB, int Mvalid, int Nvalid,
    const float* __restrict__ bias, int relu, int mode,
    __half* __restrict__ oh, float* __restrict__ of, long sO, int ldo,
    const float* __restrict__ pa, const float* __restrict__ pb)
{
    extern __shared__ char smem[];
    const uint32_t su = smem_u32(smem);
    const int tid = threadIdx.x, lane = tid & 31, wid = tid >> 5;
    const int wm = wid >> 2, wn = wid & 3;
    const int n0 = bx * 128, m0 = by * (MI * 32);
    const bool x2 = (Al != nullptr);

    const __half* A_h = Ah + (long)bz * sA + (long)m0 * ldA;
    const __half* A_l = x2 ? Al + (long)bz * sA + (long)m0 * ldA : A_h;
    const __half* B_p = B + (long)bz * sB;
    const int mMax = (Mvalid - m0 < MI * 32) ? (Mvalid - m0) : MI * 32;

    float acc[MI][4][4];
#pragma unroll
    for (int i = 0; i < MI; i++)
#pragma unroll
        for (int j = 0; j < 4; j++)
#pragma unroll
            for (int q = 0; q < 4; q++) acc[i][j][q] = 0.f;

    const int nc = K >> 5;

    auto prefetch = [&](int c, int st) {
        uint32_t sa = su + st * STAGE_BYTES;
        long kb = (long)c * 32;
#pragma unroll
        for (int i = 0; i < MI / 2; i++) {
            int idx = tid + i * 256;
            int row = idx >> 2, cc = idx & 3;
            uint32_t doff = sa + row * (APAD * 2) + cc * 16;
            bool p = row < mMax;
            cp16(doff, A_h + (long)row * ldA + kb + cc * 8, p);
            if (x2) cp16(doff + A_BYTES, A_l + (long)row * ldA + kb + cc * 8, p);
        }
#pragma unroll
        for (int i = 0; i < 2; i++) {
            int idx = tid + i * 256;
            int row = idx >> 4, cc = idx & 15;
            uint32_t doff = sa + 2 * A_BYTES + row * (BPAD * 2) + cc * 16;
            bool p = (n0 + cc * 8) < Nvalid;
            cp16(doff, B_p + (kb + row) * (long)ldB + n0 + cc * 8, p);
        }
    };

    prefetch(0, 0);
    CP_COMMIT();

    for (int c = 0; c < nc; c++) {
        CP_WAIT0();
        __syncthreads();
        if (c + 1 < nc) { prefetch(c + 1, (c + 1) & 1); CP_COMMIT(); }

        uint32_t sa = su + (c & 1) * STAGE_BYTES;
#pragma unroll
        for (int kk = 0; kk < 2; kk++) {
            uint32_t afh[MI][4], afl[MI][4];
#pragma unroll
            for (int mi = 0; mi < MI; mi++) {
                uint32_t ad = sa + ((wm * (MI * 16) + mi * 16 + (lane & 15)) * APAD
                                    + kk * 16 + (lane >> 4) * 8) * 2;
                ldmx4(afh[mi], ad);
                if (x2) ldmx4(afl[mi], ad + A_BYTES);
            }
            uint32_t bf[4][2];
#pragma unroll
            for (int ni = 0; ni < 4; ni++) {
                uint32_t bd = sa + 2 * A_BYTES
                            + (kk * 16 + (lane & 15)) * (BPAD * 2)
                            + (wn * 32 + ni * 8) * 2;
                ldmx2t(bf[ni], bd);
            }
#pragma unroll
            for (int ni = 0; ni < 4; ni++)
#pragma unroll
                for (int mi = 0; mi < MI; mi++)
                    mma16816(acc[mi][ni], afh[mi], bf[ni]);
            if (x2) {
#pragma unroll
                for (int ni = 0; ni < 4; ni++)
#pragma unroll
                    for (int mi = 0; mi < MI; mi++)
                        mma16816(acc[mi][ni], afl[mi], bf[ni]);
            }
        }
    }

    const int g = lane >> 2, tq = lane & 3;
    if (mode >= 2) {
        const float a = *pa, bb = *pb;
        const bool fast = (fabsf(a) + fabsf(bb)) <= 1.0f;
        float csum[4][2];
#pragma unroll
        for (int ni = 0; ni < 4; ni++) { csum[ni][0] = 0.f; csum[ni][1] = 0.f; }
#pragma unroll
        for (int mi = 0; mi < MI; mi++) {
            float r0 = 0.f, r1 = 0.f;
#pragma unroll
            for (int ni = 0; ni < 4; ni++) {
#pragma unroll
                for (int q = 0; q < 4; q++) {
                    float z = a * acc[mi][ni][q] + bb;
                    float s;
                    if (fast) {
                        float tt = 0.5f * z, t2 = tt * tt;
                        float th = tt * (1.f + t2 * (-0.3333333333f
                                   + t2 * (0.1333333333f - t2 * 0.05396825397f)));
                        s = 0.5f + 0.5f * th;
                    } else {
                        s = 1.f / (1.f + __expf(-z));
                    }
                    if (q < 2) r0 += s; else r1 += s;
                    csum[ni][q & 1] += s;
                }
            }
            r0 += __shfl_xor_sync(0xffffffffu, r0, 1);
            r0 += __shfl_xor_sync(0xffffffffu, r0, 2);
            r1 += __shfl_xor_sync(0xffffffffu, r1, 1);
            r1 += __shfl_xor_sync(0xffffffffu, r1, 2);
            if (tq == 0) {
                int j = m0 + wm * (MI * 16) + mi * 16 + g;
                atomicAdd(&g_bw[bz * NN + j], r0);
                atomicAdd(&g_bw[bz * NN + j + 8], r1);
            }
        }
        if (mode == 3) {
#pragma unroll
            for (int ni = 0; ni < 4; ni++) {
                float c0 = csum[ni][0], c1 = csum[ni][1];
#pragma unroll
                for (int off = 4; off < 32; off <<= 1) {
                    c0 += __shfl_xor_sync(0xffffffffu, c0, off);
                    c1 += __shfl_xor_sync(0xffffffffu, c1, off);
                }
                if (lane < 4) {
                    int col = n0 + wn * 32 + ni * 8 + lane * 2;
                    atomicAdd(&g_bw[bz * NN + col], c0);
                    atomicAdd(&g_bw[bz * NN + col + 1], c1);
                }
            }
        }
        return;
    }

#pragma unroll
    for (int mi = 0; mi < MI; mi++) {
        int r0 = m0 + wm * (MI * 16) + mi * 16 + g;
        int r1 = r0 + 8;
        float b0v = (bias && r0 < Mvalid) ? bias[r0] : 0.f;
        float b1v = (bias && r1 < Mvalid) ? bias[r1] : 0.f;
#pragma unroll
        for (int ni = 0; ni < 4; ni++) {
            int col = n0 + wn * 32 + ni * 8 + tq * 2;
            if (col >= Nvalid) continue;
            float v00 = acc[mi][ni][0] + b0v, v01 = acc[mi][ni][1] + b0v;
            float v10 = acc[mi][ni][2] + b1v, v11 = acc[mi][ni][3] + b1v;
            if (relu) {
                v00 = fmaxf(v00, 0.f); v01 = fmaxf(v01, 0.f);
                v10 = fmaxf(v10, 0.f); v11 = fmaxf(v11, 0.f);
            }
            if (mode == 0) {
                if (r0 < Mvalid) {
                    long off = (long)bz * sO + (long)r0 * ldo + col;
                    __half h0 = __float2half_rn(v00), h1 = __float2half_rn(v01);
                    *reinterpret_cast<uint32_t*>(oh + off) =
                        (uint32_t)__half_as_ushort(h0) | ((uint32_t)__half_as_ushort(h1) << 16);
                }
                if (r1 < Mvalid) {
                    long off = (long)bz * sO + (long)r1 * ldo + col;
                    __half h0 = __float2half_rn(v10), h1 = __float2half_rn(v11);
                    *reinterpret_cast<uint32_t*>(oh + off) =
                        (uint32_t)__half_as_ushort(h0) | ((uint32_t)__half_as_ushort(h1) << 16);
                }
            } else {
                if (r0 < Mvalid)
                    *reinterpret_cast<float2*>(of + (long)bz * sO + (long)r0 * ldo + col) =
                        make_float2(v00, v01);
                if (r1 < Mvalid)
                    *reinterpret_cast<float2*>(of + (long)bz * sO + (long)r1 * ldo + col) =
                        make_float2(v10, v11);
            }
        }
    }
}

// ================= GEMM1 with fused fp32->fp16 B conversion (R14, validated) =================
__device__ void gemm1_body(int bx, int by, int bz, const float* __restrict__ xf)
{
    extern __shared__ char smem[];
    const uint32_t su = smem_u32(smem);
    const int tid = threadIdx.x, lane = tid & 31, wid = tid >> 5;
    const int wm = wid >> 2, wn = wid & 3;
    const int n0 = bx * 128, m0 = by * 128;

    const __half* A_h = g_wAh + (long)m0 * NC;
    const float* xb = xf + (long)bz * NC * NN;

    float acc[4][4][4];
#pragma unroll
    for (int i = 0; i < 4; i++)
#pragma unroll
        for (int j = 0; j < 4; j++)
#pragma unroll
            for (int q = 0; q < 4; q++) acc[i][j][q] = 0.f;

    const int nc = NC >> 5;   // 48
    float4 br0[2], br1[2];

    auto prefA = [&](int c, int st) {
        uint32_t sa = su + st * STAGE_BYTES;
        long kb = (long)c * 32;
#pragma unroll
        for (int i = 0; i < 2; i++) {
            int idx = tid + i * 256;
            int row = idx >> 2, cc = idx & 3;
            cp16(sa + row * (APAD * 2) + cc * 16, A_h + (long)row * NC + kb + cc * 8, true);
        }
    };
    auto bload = [&](int c) {
        long kb = (long)c * 32;
#pragma unroll
        for (int i = 0; i < 2; i++) {
            int idx = tid + i * 256;
            int row = idx >> 4, cc = idx & 15;
            const float* s = xb + (kb + row) * (long)NN + n0 + cc * 8;
            br0[i] = *reinterpret_cast<const float4*>(s);
            br1[i] = *reinterpret_cast<const float4*>(s + 4);
        }
    };
    auto bstore = [&](int st) {
        uint32_t sa = su + st * STAGE_BYTES + 2 * A_BYTES;
#pragma unroll
        for (int i = 0; i < 2; i++) {
            int idx = tid + i * 256;
            int row = idx >> 4, cc = idx & 15;
            __half2 h0 = __floats2half2_rn(br0[i].x, br0[i].y);
            __half2 h1 = __floats2half2_rn(br0[i].z, br0[i].w);
            __half2 h2 = __floats2half2_rn(br1[i].x, br1[i].y);
            __half2 h3 = __floats2half2_rn(br1[i].z, br1[i].w);
            *reinterpret_cast<uint4*>(smem + (sa - su) + row * (BPAD * 2) + cc * 16) =
                make_uint4(*reinterpret_cast<uint32_t*>(&h0), *reinterpret_cast<uint32_t*>(&h1),
                           *reinterpret_cast<uint32_t*>(&h2), *reinterpret_cast<uint32_t*>(&h3));
        }
    };

    prefA(0, 0);
    CP_COMMIT();
    bload(0);

    for (int c = 0; c < nc; c++) {
        int st = c & 1;
        bstore(st);
        CP_WAIT0();
        __syncthreads();
        if (c + 1 < nc) { prefA(c + 1, (c + 1) & 1); CP_COMMIT(); bload(c + 1); }

        uint32_t sa = su + st * STAGE_BYTES;
#pragma unroll
        for (int kk = 0; kk < 2; kk++) {
            uint32_t afh[4][4];
#pragma unroll
            for (int mi = 0; mi < 4; mi++) {
                uint32_t ad = sa + ((wm * 64 + mi * 16 + (lane & 15)) * APAD
                                    + kk * 16 + (lane >> 4) * 8) * 2;
                ldmx4(afh[mi], ad);
            }
            uint32_t bf[4][2];
#pragma unroll
            for (int ni = 0; ni < 4; ni++) {
                uint32_t bd = sa + 2 * A_BYTES
                            + (kk * 16 + (lane & 15)) * (BPAD * 2)
                            + (wn * 32 + ni * 8) * 2;
                ldmx2t(bf[ni], bd);
            }
#pragma unroll
            for (int ni = 0; ni < 4; ni++)
#pragma unroll
                for (int mi = 0; mi < 4; mi++)
                    mma16816(acc[mi][ni], afh[mi], bf[ni]);
        }
    }

    const int g = lane >> 2, tq = lane & 3;
#pragma unroll
    for (int mi = 0; mi < 4; mi++) {
        int r0 = m0 + wm * 64 + mi * 16 + g;
        int r1 = r0 + 8;
        float b0v = g_bA[r0], b1v = g_bA[r1];
#pragma unroll
        for (int ni = 0; ni < 4; ni++) {
            int col = n0 + wn * 32 + ni * 8 + tq * 2;
            float v00 = fmaxf(acc[mi][ni][0] + b0v, 0.f);
            float v01 = fmaxf(acc[mi][ni][1] + b0v, 0.f);
            float v10 = fmaxf(acc[mi][ni][2] + b1v, 0.f);
            float v11 = fmaxf(acc[mi][ni][3] + b1v, 0.f);
            long off0 = ((long)bz * 1024 + r0) * NN + col;
            long off1 = ((long)bz * 1024 + r1) * NN + col;
            __half h0 = __float2half_rn(v00), h1 = __float2half_rn(v01);
            *reinterpret_cast<uint32_t*>(g_h + off0) =
                (uint32_t)__half_as_ushort(h0) | ((uint32_t)__half_as_ushort(h1) << 16);
            __half h2 = __float2half_rn(v10), h3 = __float2half_rn(v11);
            *reinterpret_cast<uint32_t*>(g_h + off1) =
                (uint32_t)__half_as_ushort(h2) | ((uint32_t)__half_as_ushort(h3) << 16);
        }
    }
}

// ================= small device bodies =================
__device__ void tk1_body(int bid, const float* __restrict__ t,
                         const float* __restrict__ W, const float* __restrict__ bias)
{
    int gw = (bid * 256 + threadIdx.x) >> 5;
    int lane = threadIdx.x & 31;
    int o = gw % NHID, b = gw / NHID;
    const float* tr = t + (long)b * NC;
    const float* wr = W + (long)o * NC;
    float s = 0.f;
    for (int k = lane; k < NC; k += 32) s = fmaf(tr[k], wr[k], s);
#pragma unroll
    for (int off = 16; off > 0; off >>= 1) s += __shfl_xor_sync(0xffffffffu, s, off);
    if (lane == 0) g_tht[b * NHID + o] = fmaxf(s + bias[o], 0.f);
}
__device__ void tk2_body(int bid, const float* __restrict__ W, const float* __restrict__ bias)
{
    int gw = (bid * 256 + threadIdx.x) >> 5;
    int lane = threadIdx.x & 31;
    int o = gw % NG, b = gw / NG;
    const float* hr = g_tht + (long)b * NHID;
    const float* wr = W + (long)o * NHID;
    float s = 0.f;
    for (int k = lane; k < NHID; k += 32) s = fmaf(hr[k], wr[k], s);
#pragma unroll
    for (int off = 16; off > 0; off >>= 1) s += __shfl_xor_sync(0xffffffffu, s, off);
    if (lane == 0) g_tk[b * NG + o] = s + bias[o];
}
__device__ void sk_u_body(int bid, const float* __restrict__ pdust)
{
    const float NORMC = -logf((float)(NM + NN));
    const float LOGN = logf((float)NN);
    int gw = (bid * 256 + threadIdx.x) >> 5;
    int lane = threadIdx.x & 31;
    int i = gw % (NM + 1), b = gw / (NM + 1);

    const float4* v4 = reinterpret_cast<const float4*>(g_v + b * NN);
    float xs[32];
    if (i < NM) {
        const float4* p4 = reinterpret_cast<const float4*>(g_p + ((long)b * NM + i) * NN);
#pragma unroll
        for (int w = 0; w < 8; w++) {
            float4 pv = p4[w * 32 + lane];
            float4 vv = __ldcg(v4 + w * 32 + lane);
            xs[4*w]   = pv.x + vv.x; xs[4*w+1] = pv.y + vv.y;
            xs[4*w+2] = pv.z + vv.z; xs[4*w+3] = pv.w + vv.w;
        }
    } else {
        float dust = *pdust;
#pragma unroll
        for (int w = 0; w < 8; w++) {
            float4 vv = __ldcg(v4 + w * 32 + lane);
            xs[4*w]   = dust + vv.x; xs[4*w+1] = dust + vv.y;
            xs[4*w+2] = dust + vv.z; xs[4*w+3] = dust + vv.w;
        }
    }
    float mx = xs[0];
#pragma unroll
    for (int q = 1; q < 32; q++) mx = fmaxf(mx, xs[q]);
#pragma unroll
    for (int off = 16; off > 0; off >>= 1) mx = fmaxf(mx, __shfl_xor_sync(0xffffffffu, mx, off));
    float s = 0.f;
#pragma unroll
    for (int q = 0; q < 32; q++) s += __expf(xs[q] - mx);
#pragma unroll
    for (int off = 16; off > 0; off >>= 1) s += __shfl_xor_sync(0xffffffffu, s, off);
    if (lane == 0)
        g_u[b * (NM + 1) + i] = ((i < NM) ? NORMC : (LOGN + NORMC)) - (mx + __logf(s));
}
// first u-update: v == 0
__device__ void sk_u1_body(int bid, const float* __restrict__ pdust)
{
    const float NORMC = -logf((float)(NM + NN));
    const float LOGN = logf((float)NN);
    int gw = (bid * 256 + threadIdx.x) >> 5;
    int lane = threadIdx.x & 31;
    int i = gw % (NM + 1), b = gw / (NM + 1);

    if (i == NM) {
        if (lane == 0)
            g_u[b * (NM + 1) + NM] = LOGN + NORMC - (*pdust + logf((float)NN));
        return;
    }
    const float4* p4 = reinterpret_cast<const float4*>(g_p + ((long)b * NM + i) * NN);
    float xs[32];
#pragma unroll
    for (int w = 0; w < 8; w++) {
        float4 pv = p4[w * 32 + lane];
        xs[4*w] = pv.x; xs[4*w+1] = pv.y; xs[4*w+2] = pv.z; xs[4*w+3] = pv.w;
    }
    float mx = xs[0];
#pragma unroll
    for (int q = 1; q < 32; q++) mx = fmaxf(mx, xs[q]);
#pragma unroll
    for (int off = 16; off > 0; off >>= 1) mx = fmaxf(mx, __shfl_xor_sync(0xffffffffu, mx, off));
    float s = 0.f;
#pragma unroll
    for (int q = 0; q < 32; q++) s += __expf(xs[q] - mx);
#pragma unroll
    for (int off = 16; off > 0; off >>= 1) s += __shfl_xor_sync(0xffffffffu, s, off);
    if (lane == 0)
        g_u[b * (NM + 1) + i] = NORMC - (mx + __logf(s));
}
__device__ void sk_v_body(int bid, const float* __restrict__ pdust)
{
    const float NORMC = -logf((float)(NM + NN));
    __shared__ float su[NM + 1];
    int b = bid >> 2, q = bid & 3;
    int tid = threadIdx.x;
    if (tid <= NM) su[tid] = __ldcg(&g_u[b * (NM + 1) + tid]);
    __syncthreads();
    int j = q * 256 + tid;
    const float* pb = g_p + (long)b * NM * NN + j;
    float mx = *pdust + su[NM];
    float s = 1.f;
#pragma unroll 8
    for (int i = 0; i < NM; i++) {
        float x = pb[(long)i * NN] + su[i];
        if (x > mx) { s = s * __expf(mx - x) + 1.f; mx = x; }
        else        { s += __expf(x - mx); }
    }
    g_v[b * NN + j] = NORMC - (mx + __logf(s));
    __syncthreads();
}
__device__ void convw_body(int bid, int nblk, const float* __restrict__ s,
                           __half* __restrict__ dh, int count)
{
    for (int i = bid * 256 + threadIdx.x; i < count; i += nblk * 256)
        dh[i] = __float2half_rn(s[i]);
}

// ================= merged global kernels =================
__global__ void mega_convert(const float* __restrict__ Wc1, const float* __restrict__ Ws1,
                             const float* __restrict__ Wc2, const float* __restrict__ Ws2,
                             const float* __restrict__ bc1, const float* __restrict__ bs1)
{
    int id = blockIdx.x;
    if (id < 128) {
        convw_body(id, 128, Wc1, g_wAh, NHID * NC);
    } else if (id < 256) {
        convw_body(id - 128, 128, Ws1, g_wAh + (size_t)NHID * NC, NHID * NC);
    } else if (id < 288) {
        convw_body(id - 256, 32, Wc2, g_wch, NL * NHID);
    } else if (id < 304) {
        convw_body(id - 288, 16, Ws2, g_wsh, NM * NHID);
    } else {
        for (int i = threadIdx.x; i < NHID; i += 256) {
            g_bA[i] = bc1[i];
            g_bA[NHID + i] = bs1[i];
        }
    }
}

__global__ void __launch_bounds__(256, 2) k_gemm1(
    const float* __restrict__ x,
    const float* __restrict__ t, const float* __restrict__ Wt1, const float* __restrict__ bt1)
{
    int id = blockIdx.x;
    if (id < 2048) {
        gemm1_body(id & 7, (id >> 3) & 7, id >> 6, x);
    } else {
        tk1_body(id - 2048, t, Wt1, bt1);
    }
}

__global__ void __launch_bounds__(256, 2) k_gemm2(
    const float* __restrict__ bc2, const float* __restrict__ bs2,
    const float* __restrict__ Wt2, const float* __restrict__ bt2)
{
    int id = blockIdx.x;
    if (id < 256) {
        gemm_tile<4>(id & 7, 0, id >> 3,
                     g_wch, nullptr, 0, NHID, g_h, (long)1024 * NN,
                     NHID, NN, NL, NN, bc2, 0, 0,
                     g_f, nullptr, (long)NL * NN, NN, nullptr, nullptr);
    } else if (id < 512) {
        int q = id - 256;
        gemm_tile<2>(q & 7, 0, q >> 3,
                     g_wsh, nullptr, 0, NHID, g_h + (long)NHID * NN, (long)1024 * NN,
                     NHID, NN, NM, NN, bs2, 0, 1,
                     nullptr, g_p, (long)NM * NN, NN, nullptr, nullptr);
    } else {
        tk2_body(id - 512, Wt2, bt2);
    }
}

// fnt + colnorm fused; plus zero(bw) and first Sinkhorn u-update (v==0)
__global__ void fnt2_kernel(const float* __restrict__ pdust)
{
    int id = blockIdx.x;
    if (id < 1024) {
        __shared__ float sf[128][33];
        __shared__ float part[8][32];
        __shared__ float nrm[32];
        int b = id >> 5, n0 = (id & 31) * 32;
        int tx = threadIdx.x & 31, ty = threadIdx.x >> 5;
        long fb = (long)b * NL * NN;
#pragma unroll
        for (int i = 0; i < 16; i++) {
            int l = ty + i * 8;
            sf[l][tx] = __half2float(g_f[fb + (long)l * NN + n0 + tx]);
        }
        __syncthreads();
        float s = 0.f;
#pragma unroll
        for (int i = 0; i < 16; i++) { float v2 = sf[ty * 16 + i][tx]; s = fmaf(v2, v2, s); }
        part[ty][tx] = s;
        __syncthreads();
        if (ty == 0) {
            float tot = 0.f;
#pragma unroll
            for (int i = 0; i < 8; i++) tot += part[i][tx];
            nrm[tx] = fmaxf(sqrtf(tot), 1e-12f);
        }
        __syncthreads();
#pragma unroll
        for (int i = 0; i < 16; i++) {
            int l = ty + i * 8;
            g_fnk[fb + (long)l * NN + n0 + tx] = __float2half_rn(sf[l][tx] / nrm[tx]);
        }
        int l = tx + (ty & 3) * 32;
        int rh = ty >> 2;
#pragma unroll
        for (int i = 0; i < 16; i++) {
            int r = rh * 16 + i;
            g_fnj[((long)b * NN + n0 + r) * NL + l] = __float2half_rn(sf[l][r] / nrm[r]);
        }
    } else if (id < 1152) {
        g_bw[(id - 1024) * 256 + threadIdx.x] = 0.f;
    } else {
        sk_u1_body(id - 1152, pdust);
    }
}

// Sinkhorn stage + slice of symmetric burst Gram
__global__ void __launch_bounds__(256, 2) k_burst_sk(
    int sliceStart, int skN, int phase,
    const float* __restrict__ pdust,
    const float* __restrict__ pa, const float* __restrict__ pb)
{
    int id = blockIdx.x;
    if (id < skN) {
        if (phase == 0) sk_u_body(id, pdust);
        else            sk_v_body(id, pdust);
        return;
    }
    int flat = sliceStart + (id - skN);      // 0..1151
    int bz = flat / 36;
    int rem = flat % 36;
    int jb = 0;
    while (rem >= 8 - jb) { rem -= 8 - jb; jb++; }
    int kb = jb + rem;
    gemm_tile<4>(kb, jb, bz,
                 g_fnj, nullptr, (long)NN * NL, NL, g_fnk, (long)NL * NN,
                 NL, NN, NN, NN, nullptr, 0, (jb == kb) ? 2 : 3,
                 nullptr, nullptr, 0, 0, pa, pb);
}

// transposed P finalize: thread-per-column, cterm folded, coalesced 128B stores
__global__ void pfinal2_kernel(const float* __restrict__ pbp)
{
    const float NORMC = -logf((float)(NM + NN));
    __shared__ float su[NM + 1];
    int b = blockIdx.x >> 2, q = blockIdx.x & 3;
    int tid = threadIdx.x;
    if (tid <= NM) su[tid] = g_u[b * (NM + 1) + tid];
    __syncthreads();
    int j = q * 256 + tid;
    float cv = g_v[b * NN + j] - NORMC - (*pbp) * __logf(g_bw[b * NN + j]);
    const float* pb2 = g_p + (long)b * NM * NN + j;
    uint32_t w[32];
#pragma unroll
    for (int i = 0; i < NM; i += 2) {
        float v0 = __expf(pb2[(long)i * NN] + su[i] + cv);
        float v1 = __expf(pb2[(long)(i + 1) * NN] + su[i + 1] + cv);
        __half2 hh = __floats2half2_rn(v0, v1);
        w[i >> 1] = *reinterpret_cast<uint32_t*>(&hh);
    }
    uint4* dst = reinterpret_cast<uint4*>(g_Pt + ((long)b * NN + j) * NM);
#pragma unroll
    for (int k = 0; k < 8; k++)
        dst[k] = make_uint4(w[4 * k], w[4 * k + 1], w[4 * k + 2], w[4 * k + 3]);
}

// agg split-K x4
__global__ void __launch_bounds__(256, 2) k_agg()
{
    int bz = blockIdx.x & 31, quar = blockIdx.x >> 5;
    gemm_tile<4>(0, 0, bz,
                 g_f + quar * 256, nullptr, (long)NL * NN, NN,
                 g_Pt + (long)quar * 256 * NM, (long)NN * NM,
                 256, NM, NL, NM, nullptr, 0, 1,
                 nullptr, g_aggq[quar], (long)NL * NM, NM, nullptr, nullptr);
}

__global__ void final_kernel(float* __restrict__ out)
{
    const int b = blockIdx.x, tid = threadIdx.x;
    __shared__ float sred[256];
    __shared__ float cnorm[NM];
    __shared__ float stk, stot;

    float v = g_tk[b * NG + tid];
    sred[tid] = v * v;
    __syncthreads();
    for (int s = 128; s > 0; s >>= 1) { if (tid < s) sred[tid] += sred[tid + s]; __syncthreads(); }
    if (tid == 0) stk = fmaxf(sqrtf(sred[0]), 1e-12f);
    __syncthreads();
    {
        int m = tid & 63, part = tid >> 6;
        long ab = (long)b * NL * NM;
        float s = 0.f;
        for (int l = part * 32; l < part * 32 + 32; l++) {
            long o = ab + (long)l * NM + m;
            float x = g_aggq[0][o] + g_aggq[1][o] + g_aggq[2][o] + g_aggq[3][o];
            s = fmaf(x, x, s);
        }
        sred[tid] = s;
        __syncthreads();
        if (tid < 64)
            cnorm[tid] = fmaxf(sqrtf(sred[tid] + sred[tid+64] + sred[tid+128] + sred[tid+192]), 1e-12f);
        __syncthreads();
    }
    const int ROW = NG + NL * NM;
    float* orow = out + (long)b * ROW;
    float tot = 0.f;
    for (int idx = tid; idx < ROW; idx += 256) {
        float val;
        if (idx < NG) val = g_tk[b * NG + idx] / stk;
        else {
            int r = idx - NG;
            long o = ((long)b * NL + (r >> 6)) * NM + (r & 63);
            val = (g_aggq[0][o] + g_aggq[1][o] + g_aggq[2][o] + g_aggq[3][o]) / cnorm[r & 63];
        }
        orow[idx] = val;
        tot += val * val;
    }
    sred[tid] = tot;
    __syncthreads();
    for (int s = 128; s > 0; s >>= 1) { if (tid < s) sred[tid] += sred[tid + s]; __syncthreads(); }
    if (tid == 0) stot = fmaxf(sqrtf(sred[0]), 1e-12f);
    __syncthreads();
    for (int idx = tid; idx < ROW; idx += 256) orow[idx] /= stot;
}

// ============ launcher ============
extern "C" void kernel_launch(void* const* d_in, const int* in_sizes, int n_in,
                              void* d_out, int out_size)
{
    (void)in_sizes; (void)n_in; (void)out_size;
    const float* x    = (const float*)d_in[0];
    const float* t    = (const float*)d_in[1];
    const float* Wc1  = (const float*)d_in[2];
    const float* bc1  = (const float*)d_in[3];
    const float* Wc2  = (const float*)d_in[4];
    const float* bc2  = (const float*)d_in[5];
    const float* Ws1  = (const float*)d_in[6];
    const float* bs1  = (const float*)d_in[7];
    const float* Ws2  = (const float*)d_in[8];
    const float* bs2  = (const float*)d_in[9];
    const float* Wt1  = (const float*)d_in[10];
    const float* bt1  = (const float*)d_in[11];
    const float* Wt2  = (const float*)d_in[12];
    const float* bt2  = (const float*)d_in[13];
    const float* dust = (const float*)d_in[14];
    const float* ba   = (const float*)d_in[15];
    const float* bbp  = (const float*)d_in[16];
    const float* bp   = (const float*)d_in[17];
    float* out = (float*)d_out;

    cudaFuncSetAttribute(k_gemm1,    cudaFuncAttributeMaxDynamicSharedMemorySize, SMEM_TOTAL);
    cudaFuncSetAttribute(k_gemm2,    cudaFuncAttributeMaxDynamicSharedMemorySize, SMEM_TOTAL);
    cudaFuncSetAttribute(k_burst_sk, cudaFuncAttributeMaxDynamicSharedMemorySize, SMEM_TOTAL);
    cudaFuncSetAttribute(k_agg,      cudaFuncAttributeMaxDynamicSharedMemorySize, SMEM_TOTAL);

    // 1: weight conversions + bias concat (x conversion fused into GEMM1)
    mega_convert<<<305, 256>>>(Wc1, Ws1, Wc2, Ws2, bc1, bs1);

    // 2: fused GEMM1 (in-flight x fp32->fp16) + token MLP layer 1
    k_gemm1<<<4096, 256, SMEM_TOTAL>>>(x, t, Wt1, bt1);

    // 3: GEMM2c + GEMM2s + token MLP layer 2
    k_gemm2<<<1536, 256, SMEM_TOTAL>>>(bc2, bs2, Wt2, bt2);

    // 4: fnt+colnorm + zero(bw) + Sinkhorn u1 (v==0)
    fnt2_kernel<<<1412, 256>>>(dust);

    // 5-9: burst Gram slices overlapped with remaining Sinkhorn stages (v1,u2,v2,u3,v3)
    {
        int start = 0;
        k_burst_sk<<<128 + 360, 256, SMEM_TOTAL>>>(start, 128, 1, dust, ba, bbp); start += 360;
        k_burst_sk<<<260 + 36,  256, SMEM_TOTAL>>>(start, 260, 0, dust, ba, bbp); start += 36;
        k_burst_sk<<<128 + 360, 256, SMEM_TOTAL>>>(start, 128, 1, dust, ba, bbp); start += 360;
        k_burst_sk<<<260 + 36,  256, SMEM_TOTAL>>>(start, 260, 0, dust, ba, bbp); start += 36;
        k_burst_sk<<<128 + 360, 256, SMEM_TOTAL>>>(start, 128, 1, dust, ba, bbp);
    }

    // 10: transport plan (transposed, cterm folded)
    pfinal2_kernel<<<128, 256>>>(bp);

    // 11-12: aggregation (split-K x4) + final normalize
    k_agg<<<128, 256, SMEM_TOTAL>>>();
    final_kernel<<<NB, 256>>>(out);
}

// round 17
// speedup vs baseline: 1.0601x; 1.0169x over previous
#include <cuda_runtime.h>
#include <cuda_fp16.h>
#include <math.h>
#include <stdint.h>

#define NB 32
#define NC 1536
#define NN 1024
#define NHID 512
#define NL 128
#define NM 64
#define NG 256

#define APAD 40
#define BPAD 136
#define A_BYTES (128 * APAD * 2)
#define B_BYTES (32 * BPAD * 2)
#define STAGE_BYTES (2 * A_BYTES + B_BYTES)
#define SMEM_TOTAL (2 * STAGE_BYTES)        // 58368

// ---- scratch ----
__device__ __half g_h  [(size_t)NB * 1024 * NN];
__device__ __half g_f  [(size_t)NB * NL * NN];
__device__ __half g_fnj[(size_t)NB * NN * NL];
__device__ __half g_fnk[(size_t)NB * NL * NN];
__device__ float  g_p  [(size_t)NB * NM * NN];
__device__ __half g_Pt [(size_t)NB * NN * NM];
__device__ __half g_wAh[1024 * NC];
__device__ float  g_bA [1024];
__device__ __half g_wch[NL * NHID];
__device__ __half g_wsh[NM * NHID];
__device__ float g_u[NB * (NM + 1)];
__device__ float g_v[NB * NN];
__device__ float g_bw[NB * NN];
__device__ float g_aggq[4][(size_t)NB * NL * NM];
__device__ float g_tht[NB * NHID];
__device__ float g_tk[NB * NG];

__device__ __forceinline__ uint32_t smem_u32(const void* p) {
    uint32_t a;
    asm("{ .reg .u64 t; cvta.to.shared.u64 t, %1; cvt.u32.u64 %0, t; }" : "=r"(a) : "l"(p));
    return a;
}
__device__ __forceinline__ void cp16(uint32_t d, const void* s, bool pred) {
    int sz = pred ? 16 : 0;
    asm volatile("cp.async.cg.shared.global [%0], [%1], 16, %2;"
                 :: "r"(d), "l"(s), "r"(sz) : "memory");
}
#define CP_COMMIT() asm volatile("cp.async.commit_group;" ::: "memory")
#define CP_WAIT0()  asm volatile("cp.async.wait_group 0;" ::: "memory")

__device__ __forceinline__ void ldmx4(uint32_t* r, uint32_t a) {
    asm volatile("ldmatrix.sync.aligned.m8n8.x4.shared.b16 {%0,%1,%2,%3}, [%4];"
        : "=r"(r[0]), "=r"(r[1]), "=r"(r[2]), "=r"(r[3]) : "r"(a));
}
__device__ __forceinline__ void ldmx2t(uint32_t* r, uint32_t a) {
    asm volatile("ldmatrix.sync.aligned.m8n8.x2.trans.shared.b16 {%0,%1}, [%2];"
        : "=r"(r[0]), "=r"(r[1]) : "r"(a));
}
__device__ __forceinline__ void mma16816(float* d, const uint32_t* a, const uint32_t* b) {
    asm volatile("mma.sync.aligned.m16n8k16.row.col.f32.f16.f16.f32 "
        "{%0,%1,%2,%3}, {%4,%5,%6,%7}, {%8,%9}, {%0,%1,%2,%3};"
        : "+f"(d[0]), "+f"(d[1]), "+f"(d[2]), "+f"(d[3])
        : "r"(a[0]), "r"(a[1]), "r"(a[2]), "r"(a[3]), "r"(b[0]), "r"(b[1]));
}

// ================= generic GEMM tile (validated) =================
template<int MI>
__device__ void gemm_tile(
    int bx, int by, int bz,
    const __half* __restrict__ Ah, const __half* __restrict__ Al, long sA, int ldA,
    const __half* __restrict__ B, long sB,
    int K, int ldB, int Mvalid, int Nvalid,
    const float* __restrict__ bias, int relu, int mode,
    __half* __restrict__ oh, float* __restrict__ of, long sO, int ldo,
    const float* __restrict__ pa, const float* __restrict__ pb)
{
    extern __shared__ char smem[];
    const uint32_t su = smem_u32(smem);
    const int tid = threadIdx.x, lane = tid & 31, wid = tid >> 5;
    const int wm = wid >> 2, wn = wid & 3;
    const int n0 = bx * 128, m0 = by * (MI * 32);
    const bool x2 = (Al != nullptr);

    const __half* A_h = Ah + (long)bz * sA + (long)m0 * ldA;
    const __half* A_l = x2 ? Al + (long)bz * sA + (long)m0 * ldA : A_h;
    const __half* B_p = B + (long)bz * sB;
    const int mMax = (Mvalid - m0 < MI * 32) ? (Mvalid - m0) : MI * 32;

    float acc[MI][4][4];
#pragma unroll
    for (int i = 0; i < MI; i++)
#pragma unroll
        for (int j = 0; j < 4; j++)
#pragma unroll
            for (int q = 0; q < 4; q++) acc[i][j][q] = 0.f;

    const int nc = K >> 5;

    auto prefetch = [&](int c, int st) {
        uint32_t sa = su + st * STAGE_BYTES;
        long kb = (long)c * 32;
#pragma unroll
        for (int i = 0; i < MI / 2; i++) {
            int idx = tid + i * 256;
            int row = idx >> 2, cc = idx & 3;
            uint32_t doff = sa + row * (APAD * 2) + cc * 16;
            bool p = row < mMax;
            cp16(doff, A_h + (long)row * ldA + kb + cc * 8, p);
            if (x2) cp16(doff + A_BYTES, A_l + (long)row * ldA + kb + cc * 8, p);
        }
#pragma unroll
        for (int i = 0; i < 2; i++) {
            int idx = tid + i * 256;
            int row = idx >> 4, cc = idx & 15;
            uint32_t doff = sa + 2 * A_BYTES + row * (BPAD * 2) + cc * 16;
            bool p = (n0 + cc * 8) < Nvalid;
            cp16(doff, B_p + (kb + row) * (long)ldB + n0 + cc * 8, p);
        }
    };

    prefetch(0, 0);
    CP_COMMIT();

    for (int c = 0; c < nc; c++) {
        CP_WAIT0();
        __syncthreads();
        if (c + 1 < nc) { prefetch(c + 1, (c + 1) & 1); CP_COMMIT(); }

        uint32_t sa = su + (c & 1) * STAGE_BYTES;
#pragma unroll
        for (int kk = 0; kk < 2; kk++) {
            uint32_t afh[MI][4], afl[MI][4];
#pragma unroll
            for (int mi = 0; mi < MI; mi++) {
                uint32_t ad = sa + ((wm * (MI * 16) + mi * 16 + (lane & 15)) * APAD
                                    + kk * 16 + (lane >> 4) * 8) * 2;
                ldmx4(afh[mi], ad);
                if (x2) ldmx4(afl[mi], ad + A_BYTES);
            }
            uint32_t bf[4][2];
#pragma unroll
            for (int ni = 0; ni < 4; ni++) {
                uint32_t bd = sa + 2 * A_BYTES
                            + (kk * 16 + (lane & 15)) * (BPAD * 2)
                            + (wn * 32 + ni * 8) * 2;
                ldmx2t(bf[ni], bd);
            }
#pragma unroll
            for (int ni = 0; ni < 4; ni++)
#pragma unroll
                for (int mi = 0; mi < MI; mi++)
                    mma16816(acc[mi][ni], afh[mi], bf[ni]);
            if (x2) {
#pragma unroll
                for (int ni = 0; ni < 4; ni++)
#pragma unroll
                    for (int mi = 0; mi < MI; mi++)
                        mma16816(acc[mi][ni], afl[mi], bf[ni]);
            }
        }
    }

    const int g = lane >> 2, tq = lane & 3;
    if (mode >= 2) {
        const float a = *pa, bb = *pb;
        const bool fast = (fabsf(a) + fabsf(bb)) <= 1.0f;
        float csum[4][2];
#pragma unroll
        for (int ni = 0; ni < 4; ni++) { csum[ni][0] = 0.f; csum[ni][1] = 0.f; }
#pragma unroll
        for (int mi = 0; mi < MI; mi++) {
            float r0 = 0.f, r1 = 0.f;
#pragma unroll
            for (int ni = 0; ni < 4; ni++) {
#pragma unroll
                for (int q = 0; q < 4; q++) {
                    float z = a * acc[mi][ni][q] + bb;
                    float s;
                    if (fast) {
                        float tt = 0.5f * z, t2 = tt * tt;
                        float th = tt * (1.f + t2 * (-0.3333333333f
                                   + t2 * (0.1333333333f - t2 * 0.05396825397f)));
                        s = 0.5f + 0.5f * th;
                    } else {
                        s = 1.f / (1.f + __expf(-z));
                    }
                    if (q < 2) r0 += s; else r1 += s;
                    csum[ni][q & 1] += s;
                }
            }
            r0 += __shfl_xor_sync(0xffffffffu, r0, 1);
            r0 += __shfl_xor_sync(0xffffffffu, r0, 2);
            r1 += __shfl_xor_sync(0xffffffffu, r1, 1);
            r1 += __shfl_xor_sync(0xffffffffu, r1, 2);
            if (tq == 0) {
                int j = m0 + wm * (MI * 16) + mi * 16 + g;
                atomicAdd(&g_bw[bz * NN + j], r0);
                atomicAdd(&g_bw[bz * NN + j + 8], r1);
            }
        }
        if (mode == 3) {
#pragma unroll
            for (int ni = 0; ni < 4; ni++) {
                float c0 = csum[ni][0], c1 = csum[ni][1];
#pragma unroll
                for (int off = 4; off < 32; off <<= 1) {
                    c0 += __shfl_xor_sync(0xffffffffu, c0, off);
                    c1 += __shfl_xor_sync(0xffffffffu, c1, off);
                }
                if (lane < 4) {
                    int col = n0 + wn * 32 + ni * 8 + lane * 2;
                    atomicAdd(&g_bw[bz * NN + col], c0);
                    atomicAdd(&g_bw[bz * NN + col + 1], c1);
                }
            }
        }
        return;
    }

#pragma unroll
    for (int mi = 0; mi < MI; mi++) {
        int r0 = m0 + wm * (MI * 16) + mi * 16 + g;
        int r1 = r0 + 8;
        float b0v = (bias && r0 < Mvalid) ? bias[r0] : 0.f;
        float b1v = (bias && r1 < Mvalid) ? bias[r1] : 0.f;
#pragma unroll
        for (int ni = 0; ni < 4; ni++) {
            int col = n0 + wn * 32 + ni * 8 + tq * 2;
            if (col >= Nvalid) continue;
            float v00 = acc[mi][ni][0] + b0v, v01 = acc[mi][ni][1] + b0v;
            float v10 = acc[mi][ni][2] + b1v, v11 = acc[mi][ni][3] + b1v;
            if (relu) {
                v00 = fmaxf(v00, 0.f); v01 = fmaxf(v01, 0.f);
                v10 = fmaxf(v10, 0.f); v11 = fmaxf(v11, 0.f);
            }
            if (mode == 0) {
                if (r0 < Mvalid) {
                    long off = (long)bz * sO + (long)r0 * ldo + col;
                    __half h0 = __float2half_rn(v00), h1 = __float2half_rn(v01);
                    *reinterpret_cast<uint32_t*>(oh + off) =
                        (uint32_t)__half_as_ushort(h0) | ((uint32_t)__half_as_ushort(h1) << 16);
                }
                if (r1 < Mvalid) {
                    long off = (long)bz * sO + (long)r1 * ldo + col;
                    __half h0 = __float2half_rn(v10), h1 = __float2half_rn(v11);
                    *reinterpret_cast<uint32_t*>(oh + off) =
                        (uint32_t)__half_as_ushort(h0) | ((uint32_t)__half_as_ushort(h1) << 16);
                }
            } else {
                if (r0 < Mvalid)
                    *reinterpret_cast<float2*>(of + (long)bz * sO + (long)r0 * ldo + col) =
                        make_float2(v00, v01);
                if (r1 < Mvalid)
                    *reinterpret_cast<float2*>(of + (long)bz * sO + (long)r1 * ldo + col) =
                        make_float2(v10, v11);
            }
        }
    }
}

// ================= GEMM1 with fused fp32->fp16 B conversion (validated) =================
__device__ void gemm1_body(int bx, int by, int bz, const float* __restrict__ xf)
{
    extern __shared__ char smem[];
    const uint32_t su = smem_u32(smem);
    const int tid = threadIdx.x, lane = tid & 31, wid = tid >> 5;
    const int wm = wid >> 2, wn = wid & 3;
    const int n0 = bx * 128, m0 = by * 128;

    const __half* A_h = g_wAh + (long)m0 * NC;
    const float* xb = xf + (long)bz * NC * NN;

    float acc[4][4][4];
#pragma unroll
    for (int i = 0; i < 4; i++)
#pragma unroll
        for (int j = 0; j < 4; j++)
#pragma unroll
            for (int q = 0; q < 4; q++) acc[i][j][q] = 0.f;

    const int nc = NC >> 5;   // 48
    float4 br0[2], br1[2];

    auto prefA = [&](int c, int st) {
        uint32_t sa = su + st * STAGE_BYTES;
        long kb = (long)c * 32;
#pragma unroll
        for (int i = 0; i < 2; i++) {
            int idx = tid + i * 256;
            int row = idx >> 2, cc = idx & 3;
            cp16(sa + row * (APAD * 2) + cc * 16, A_h + (long)row * NC + kb + cc * 8, true);
        }
    };
    auto bload = [&](int c) {
        long kb = (long)c * 32;
#pragma unroll
        for (int i = 0; i < 2; i++) {
            int idx = tid + i * 256;
            int row = idx >> 4, cc = idx & 15;
            const float* s = xb + (kb + row) * (long)NN + n0 + cc * 8;
            br0[i] = *reinterpret_cast<const float4*>(s);
            br1[i] = *reinterpret_cast<const float4*>(s + 4);
        }
    };
    auto bstore = [&](int st) {
        uint32_t sa = su + st * STAGE_BYTES + 2 * A_BYTES;
#pragma unroll
        for (int i = 0; i < 2; i++) {
            int idx = tid + i * 256;
            int row = idx >> 4, cc = idx & 15;
            __half2 h0 = __floats2half2_rn(br0[i].x, br0[i].y);
            __half2 h1 = __floats2half2_rn(br0[i].z, br0[i].w);
            __half2 h2 = __floats2half2_rn(br1[i].x, br1[i].y);
            __half2 h3 = __floats2half2_rn(br1[i].z, br1[i].w);
            *reinterpret_cast<uint4*>(smem + (sa - su) + row * (BPAD * 2) + cc * 16) =
                make_uint4(*reinterpret_cast<uint32_t*>(&h0), *reinterpret_cast<uint32_t*>(&h1),
                           *reinterpret_cast<uint32_t*>(&h2), *reinterpret_cast<uint32_t*>(&h3));
        }
    };

    prefA(0, 0);
    CP_COMMIT();
    bload(0);

    for (int c = 0; c < nc; c++) {
        int st = c & 1;
        bstore(st);
        CP_WAIT0();
        __syncthreads();
        if (c + 1 < nc) { prefA(c + 1, (c + 1) & 1); CP_COMMIT(); bload(c + 1); }

        uint32_t sa = su + st * STAGE_BYTES;
#pragma unroll
        for (int kk = 0; kk < 2; kk++) {
            uint32_t afh[4][4];
#pragma unroll
            for (int mi = 0; mi < 4; mi++) {
                uint32_t ad = sa + ((wm * 64 + mi * 16 + (lane & 15)) * APAD
                                    + kk * 16 + (lane >> 4) * 8) * 2;
                ldmx4(afh[mi], ad);
            }
            uint32_t bf[4][2];
#pragma unroll
            for (int ni = 0; ni < 4; ni++) {
                uint32_t bd = sa + 2 * A_BYTES
                            + (kk * 16 + (lane & 15)) * (BPAD * 2)
                            + (wn * 32 + ni * 8) * 2;
                ldmx2t(bf[ni], bd);
            }
#pragma unroll
            for (int ni = 0; ni < 4; ni++)
#pragma unroll
                for (int mi = 0; mi < 4; mi++)
                    mma16816(acc[mi][ni], afh[mi], bf[ni]);
        }
    }

    const int g = lane >> 2, tq = lane & 3;
#pragma unroll
    for (int mi = 0; mi < 4; mi++) {
        int r0 = m0 + wm * 64 + mi * 16 + g;
        int r1 = r0 + 8;
        float b0v = g_bA[r0], b1v = g_bA[r1];
#pragma unroll
        for (int ni = 0; ni < 4; ni++) {
            int col = n0 + wn * 32 + ni * 8 + tq * 2;
            float v00 = fmaxf(acc[mi][ni][0] + b0v, 0.f);
            float v01 = fmaxf(acc[mi][ni][1] + b0v, 0.f);
            float v10 = fmaxf(acc[mi][ni][2] + b1v, 0.f);
            float v11 = fmaxf(acc[mi][ni][3] + b1v, 0.f);
            long off0 = ((long)bz * 1024 + r0) * NN + col;
            long off1 = ((long)bz * 1024 + r1) * NN + col;
            __half h0 = __float2half_rn(v00), h1 = __float2half_rn(v01);
            *reinterpret_cast<uint32_t*>(g_h + off0) =
                (uint32_t)__half_as_ushort(h0) | ((uint32_t)__half_as_ushort(h1) << 16);
            __half h2 = __float2half_rn(v10), h3 = __float2half_rn(v11);
            *reinterpret_cast<uint32_t*>(g_h + off1) =
                (uint32_t)__half_as_ushort(h2) | ((uint32_t)__half_as_ushort(h3) << 16);
        }
    }
}

// ================= small device bodies =================
__device__ void tk1_body(int bid, const float* __restrict__ t,
                         const float* __restrict__ W, const float* __restrict__ bias)
{
    int gw = (bid * 256 + threadIdx.x) >> 5;
    int lane = threadIdx.x & 31;
    int o = gw % NHID, b = gw / NHID;
    const float* tr = t + (long)b * NC;
    const float* wr = W + (long)o * NC;
    float s = 0.f;
    for (int k = lane; k < NC; k += 32) s = fmaf(tr[k], wr[k], s);
#pragma unroll
    for (int off = 16; off > 0; off >>= 1) s += __shfl_xor_sync(0xffffffffu, s, off);
    if (lane == 0) g_tht[b * NHID + o] = fmaxf(s + bias[o], 0.f);
}
__device__ void tk2_body(int bid, const float* __restrict__ W, const float* __restrict__ bias)
{
    int gw = (bid * 256 + threadIdx.x) >> 5;
    int lane = threadIdx.x & 31;
    int o = gw % NG, b = gw / NG;
    const float* hr = g_tht + (long)b * NHID;
    const float* wr = W + (long)o * NHID;
    float s = 0.f;
    for (int k = lane; k < NHID; k += 32) s = fmaf(hr[k], wr[k], s);
#pragma unroll
    for (int off = 16; off > 0; off >>= 1) s += __shfl_xor_sync(0xffffffffu, s, off);
    if (lane == 0) g_tk[b * NG + o] = s + bias[o];
}
__device__ void sk_u_body(int bid, const float* __restrict__ pdust)
{
    const float NORMC = -logf((float)(NM + NN));
    const float LOGN = logf((float)NN);
    int gw = (bid * 256 + threadIdx.x) >> 5;
    int lane = threadIdx.x & 31;
    int i = gw % (NM + 1), b = gw / (NM + 1);

    const float4* v4 = reinterpret_cast<const float4*>(g_v + b * NN);
    float xs[32];
    if (i < NM) {
        const float4* p4 = reinterpret_cast<const float4*>(g_p + ((long)b * NM + i) * NN);
#pragma unroll
        for (int w = 0; w < 8; w++) {
            float4 pv = p4[w * 32 + lane];
            float4 vv = __ldcg(v4 + w * 32 + lane);
            xs[4*w]   = pv.x + vv.x; xs[4*w+1] = pv.y + vv.y;
            xs[4*w+2] = pv.z + vv.z; xs[4*w+3] = pv.w + vv.w;
        }
    } else {
        float dust = *pdust;
#pragma unroll
        for (int w = 0; w < 8; w++) {
            float4 vv = __ldcg(v4 + w * 32 + lane);
            xs[4*w]   = dust + vv.x; xs[4*w+1] = dust + vv.y;
            xs[4*w+2] = dust + vv.z; xs[4*w+3] = dust + vv.w;
        }
    }
    float mx = xs[0];
#pragma unroll
    for (int q = 1; q < 32; q++) mx = fmaxf(mx, xs[q]);
#pragma unroll
    for (int off = 16; off > 0; off >>= 1) mx = fmaxf(mx, __shfl_xor_sync(0xffffffffu, mx, off));
    float s = 0.f;
#pragma unroll
    for (int q = 0; q < 32; q++) s += __expf(xs[q] - mx);
#pragma unroll
    for (int off = 16; off > 0; off >>= 1) s += __shfl_xor_sync(0xffffffffu, s, off);
    if (lane == 0)
        g_u[b * (NM + 1) + i] = ((i < NM) ? NORMC : (LOGN + NORMC)) - (mx + __logf(s));
}
// first u-update: v == 0
__device__ void sk_u1_body(int bid, const float* __restrict__ pdust)
{
    const float NORMC = -logf((float)(NM + NN));
    const float LOGN = logf((float)NN);
    int gw = (bid * 256 + threadIdx.x) >> 5;
    int lane = threadIdx.x & 31;
    int i = gw % (NM + 1), b = gw / (NM + 1);

    if (i == NM) {
        if (lane == 0)
            g_u[b * (NM + 1) + NM] = LOGN + NORMC - (*pdust + logf((float)NN));
        return;
    }
    const float4* p4 = reinterpret_cast<const float4*>(g_p + ((long)b * NM + i) * NN);
    float xs[32];
#pragma unroll
    for (int w = 0; w < 8; w++) {
        float4 pv = p4[w * 32 + lane];
        xs[4*w] = pv.x; xs[4*w+1] = pv.y; xs[4*w+2] = pv.z; xs[4*w+3] = pv.w;
    }
    float mx = xs[0];
#pragma unroll
    for (int q = 1; q < 32; q++) mx = fmaxf(mx, xs[q]);
#pragma unroll
    for (int off = 16; off > 0; off >>= 1) mx = fmaxf(mx, __shfl_xor_sync(0xffffffffu, mx, off));
    float s = 0.f;
#pragma unroll
    for (int q = 0; q < 32; q++) s += __expf(xs[q] - mx);
#pragma unroll
    for (int off = 16; off > 0; off >>= 1) s += __shfl_xor_sync(0xffffffffu, s, off);
    if (lane == 0)
        g_u[b * (NM + 1) + i] = NORMC - (mx + __logf(s));
}
__device__ void sk_v_body(int bid, const float* __restrict__ pdust)
{
    const float NORMC = -logf((float)(NM + NN));
    __shared__ float su[NM + 1];
    int b = bid >> 2, q = bid & 3;
    int tid = threadIdx.x;
    if (tid <= NM) su[tid] = __ldcg(&g_u[b * (NM + 1) + tid]);
    __syncthreads();
    int j = q * 256 + tid;
    const float* pb = g_p + (long)b * NM * NN + j;
    float mx = *pdust + su[NM];
    float s = 1.f;
#pragma unroll 8
    for (int i = 0; i < NM; i++) {
        float x = pb[(long)i * NN] + su[i];
        if (x > mx) { s = s * __expf(mx - x) + 1.f; mx = x; }
        else        { s += __expf(x - mx); }
    }
    g_v[b * NN + j] = NORMC - (mx + __logf(s));
    __syncthreads();
}
__device__ void convw_body(int bid, int nblk, const float* __restrict__ s,
                           __half* __restrict__ dh, int count)
{
    for (int i = bid * 256 + threadIdx.x; i < count; i += nblk * 256)
        dh[i] = __float2half_rn(s[i]);
}

// ================= merged global kernels =================
__global__ void mega_convert(const float* __restrict__ Wc1, const float* __restrict__ Ws1,
                             const float* __restrict__ Wc2, const float* __restrict__ Ws2,
                             const float* __restrict__ bc1, const float* __restrict__ bs1)
{
    int id = blockIdx.x;
    if (id < 128) {
        convw_body(id, 128, Wc1, g_wAh, NHID * NC);
    } else if (id < 256) {
        convw_body(id - 128, 128, Ws1, g_wAh + (size_t)NHID * NC, NHID * NC);
    } else if (id < 288) {
        convw_body(id - 256, 32, Wc2, g_wch, NL * NHID);
    } else if (id < 304) {
        convw_body(id - 288, 16, Ws2, g_wsh, NM * NHID);
    } else {
        for (int i = threadIdx.x; i < NHID; i += 256) {
            g_bA[i] = bc1[i];
            g_bA[NHID + i] = bs1[i];
        }
    }
}

__global__ void __launch_bounds__(256, 2) k_gemm1(
    const float* __restrict__ x,
    const float* __restrict__ t, const float* __restrict__ Wt1, const float* __restrict__ bt1)
{
    int id = blockIdx.x;
    if (id < 2048) {
        gemm1_body(id & 7, (id >> 3) & 7, id >> 6, x);
    } else {
        tk1_body(id - 2048, t, Wt1, bt1);
    }
}

__global__ void __launch_bounds__(256, 2) k_gemm2(
    const float* __restrict__ bc2, const float* __restrict__ bs2,
    const float* __restrict__ Wt2, const float* __restrict__ bt2)
{
    int id = blockIdx.x;
    if (id < 256) {
        gemm_tile<4>(id & 7, 0, id >> 3,
                     g_wch, nullptr, 0, NHID, g_h, (long)1024 * NN,
                     NHID, NN, NL, NN, bc2, 0, 0,
                     g_f, nullptr, (long)NL * NN, NN, nullptr, nullptr);
    } else if (id < 512) {
        int q = id - 256;
        gemm_tile<2>(q & 7, 0, q >> 3,
                     g_wsh, nullptr, 0, NHID, g_h + (long)NHID * NN, (long)1024 * NN,
                     NHID, NN, NM, NN, bs2, 0, 1,
                     nullptr, g_p, (long)NM * NN, NN, nullptr, nullptr);
    } else {
        tk2_body(id - 512, Wt2, bt2);
    }
}

// fnt + colnorm fused; plus zero(bw) and first Sinkhorn u-update (v==0)
__global__ void fnt2_kernel(const float* __restrict__ pdust)
{
    int id = blockIdx.x;
    if (id < 1024) {
        __shared__ float sf[128][33];
        __shared__ float part[8][32];
        __shared__ float nrm[32];
        int b = id >> 5, n0 = (id & 31) * 32;
        int tx = threadIdx.x & 31, ty = threadIdx.x >> 5;
        long fb = (long)b * NL * NN;
#pragma unroll
        for (int i = 0; i < 16; i++) {
            int l = ty + i * 8;
            sf[l][tx] = __half2float(g_f[fb + (long)l * NN + n0 + tx]);
        }
        __syncthreads();
        float s = 0.f;
#pragma unroll
        for (int i = 0; i < 16; i++) { float v2 = sf[ty * 16 + i][tx]; s = fmaf(v2, v2, s); }
        part[ty][tx] = s;
        __syncthreads();
        if (ty == 0) {
            float tot = 0.f;
#pragma unroll
            for (int i = 0; i < 8; i++) tot += part[i][tx];
            nrm[tx] = fmaxf(sqrtf(tot), 1e-12f);
        }
        __syncthreads();
#pragma unroll
        for (int i = 0; i < 16; i++) {
            int l = ty + i * 8;
            g_fnk[fb + (long)l * NN + n0 + tx] = __float2half_rn(sf[l][tx] / nrm[tx]);
        }
        int l = tx + (ty & 3) * 32;
        int rh = ty >> 2;
#pragma unroll
        for (int i = 0; i < 16; i++) {
            int r = rh * 16 + i;
            g_fnj[((long)b * NN + n0 + r) * NL + l] = __float2half_rn(sf[l][r] / nrm[r]);
        }
    } else if (id < 1152) {
        g_bw[(id - 1024) * 256 + threadIdx.x] = 0.f;
    } else {
        sk_u1_body(id - 1152, pdust);
    }
}

// Sinkhorn stage + slice of symmetric burst Gram
__global__ void __launch_bounds__(256, 2) k_burst_sk(
    int sliceStart, int skN, int phase,
    const float* __restrict__ pdust,
    const float* __restrict__ pa, const float* __restrict__ pb)
{
    int id = blockIdx.x;
    if (id < skN) {
        if (phase == 0) sk_u_body(id, pdust);
        else            sk_v_body(id, pdust);
        return;
    }
    int flat = sliceStart + (id - skN);      // 0..1151
    int bz = flat / 36;
    int rem = flat % 36;
    int jb = 0;
    while (rem >= 8 - jb) { rem -= 8 - jb; jb++; }
    int kb = jb + rem;
    gemm_tile<4>(kb, jb, bz,
                 g_fnj, nullptr, (long)NN * NL, NL, g_fnk, (long)NL * NN,
                 NL, NN, NN, NN, nullptr, 0, (jb == kb) ? 2 : 3,
                 nullptr, nullptr, 0, 0, pa, pb);
}

// P finalize with FUSED final v-update (v3): thread-per-column,
// pass 1 computes v3 via online-lse over the same p-column pass 2 re-reads.
__global__ void pfinal3_kernel(const float* __restrict__ pdust,
                               const float* __restrict__ pbp)
{
    const float NORMC = -logf((float)(NM + NN));
    __shared__ float su[NM + 1];
    int b = blockIdx.x >> 2, q = blockIdx.x & 3;
    int tid = threadIdx.x;
    if (tid <= NM) su[tid] = g_u[b * (NM + 1) + tid];
    __syncthreads();
    int j = q * 256 + tid;
    const float* pb2 = g_p + (long)b * NM * NN + j;

    // pass 1: v3_j = NORMC - lse_i(p[i][j] + u[i]) with dust row — identical
    // iteration order to sk_v_body for bit-stable results
    float mx = *pdust + su[NM];
    float s = 1.f;
#pragma unroll 8
    for (int i = 0; i < NM; i++) {
        float x = pb2[(long)i * NN] + su[i];
        if (x > mx) { s = s * __expf(mx - x) + 1.f; mx = x; }
        else        { s += __expf(x - mx); }
    }
    float v3 = NORMC - (mx + __logf(s));
    float cv = v3 - NORMC - (*pbp) * __logf(g_bw[b * NN + j]);

    // pass 2: P^T fp16, coalesced 128B stores
    uint32_t w[32];
#pragma unroll
    for (int i = 0; i < NM; i += 2) {
        float v0 = __expf(pb2[(long)i * NN] + su[i] + cv);
        float v1 = __expf(pb2[(long)(i + 1) * NN] + su[i + 1] + cv);
        __half2 hh = __floats2half2_rn(v0, v1);
        w[i >> 1] = *reinterpret_cast<uint32_t*>(&hh);
    }
    uint4* dst = reinterpret_cast<uint4*>(g_Pt + ((long)b * NN + j) * NM);
#pragma unroll
    for (int k = 0; k < 8; k++)
        dst[k] = make_uint4(w[4 * k], w[4 * k + 1], w[4 * k + 2], w[4 * k + 3]);
}

// agg split-K x4
__global__ void __launch_bounds__(256, 2) k_agg()
{
    int bz = blockIdx.x & 31, quar = blockIdx.x >> 5;
    gemm_tile<4>(0, 0, bz,
                 g_f + quar * 256, nullptr, (long)NL * NN, NN,
                 g_Pt + (long)quar * 256 * NM, (long)NN * NM,
                 256, NM, NL, NM, nullptr, 0, 1,
                 nullptr, g_aggq[quar], (long)NL * NM, NM, nullptr, nullptr);
}

__global__ void final_kernel(float* __restrict__ out)
{
    const int b = blockIdx.x, tid = threadIdx.x;
    __shared__ float sred[256];
    __shared__ float cnorm[NM];
    __shared__ float stk, stot;

    float v = g_tk[b * NG + tid];
    sred[tid] = v * v;
    __syncthreads();
    for (int s = 128; s > 0; s >>= 1) { if (tid < s) sred[tid] += sred[tid + s]; __syncthreads(); }
    if (tid == 0) stk = fmaxf(sqrtf(sred[0]), 1e-12f);
    __syncthreads();
    {
        int m = tid & 63, part = tid >> 6;
        long ab = (long)b * NL * NM;
        float s = 0.f;
        for (int l = part * 32; l < part * 32 + 32; l++) {
            long o = ab + (long)l * NM + m;
            float x = g_aggq[0][o] + g_aggq[1][o] + g_aggq[2][o] + g_aggq[3][o];
            s = fmaf(x, x, s);
        }
        sred[tid] = s;
        __syncthreads();
        if (tid < 64)
            cnorm[tid] = fmaxf(sqrtf(sred[tid] + sred[tid+64] + sred[tid+128] + sred[tid+192]), 1e-12f);
        __syncthreads();
    }
    const int ROW = NG + NL * NM;
    float* orow = out + (long)b * ROW;
    float tot = 0.f;
    for (int idx = tid; idx < ROW; idx += 256) {
        float val;
        if (idx < NG) val = g_tk[b * NG + idx] / stk;
        else {
            int r = idx - NG;
            long o = ((long)b * NL + (r >> 6)) * NM + (r & 63);
            val = (g_aggq[0][o] + g_aggq[1][o] + g_aggq[2][o] + g_aggq[3][o]) / cnorm[r & 63];
        }
        orow[idx] = val;
        tot += val * val;
    }
    sred[tid] = tot;
    __syncthreads();
    for (int s = 128; s > 0; s >>= 1) { if (tid < s) sred[tid] += sred[tid + s]; __syncthreads(); }
    if (tid == 0) stot = fmaxf(sqrtf(sred[0]), 1e-12f);
    __syncthreads();
    for (int idx = tid; idx < ROW; idx += 256) orow[idx] /= stot;
}

// ============ launcher ============
extern "C" void kernel_launch(void* const* d_in, const int* in_sizes, int n_in,
                              void* d_out, int out_size)
{
    (void)in_sizes; (void)n_in; (void)out_size;
    const float* x    = (const float*)d_in[0];
    const float* t    = (const float*)d_in[1];
    const float* Wc1  = (const float*)d_in[2];
    const float* bc1  = (const float*)d_in[3];
    const float* Wc2  = (const float*)d_in[4];
    const float* bc2  = (const float*)d_in[5];
    const float* Ws1  = (const float*)d_in[6];
    const float* bs1  = (const float*)d_in[7];
    const float* Ws2  = (const float*)d_in[8];
    const float* bs2  = (const float*)d_in[9];
    const float* Wt1  = (const float*)d_in[10];
    const float* bt1  = (const float*)d_in[11];
    const float* Wt2  = (const float*)d_in[12];
    const float* bt2  = (const float*)d_in[13];
    const float* dust = (const float*)d_in[14];
    const float* ba   = (const float*)d_in[15];
    const float* bbp  = (const float*)d_in[16];
    const float* bp   = (const float*)d_in[17];
    float* out = (float*)d_out;

    cudaFuncSetAttribute(k_gemm1,    cudaFuncAttributeMaxDynamicSharedMemorySize, SMEM_TOTAL);
    cudaFuncSetAttribute(k_gemm2,    cudaFuncAttributeMaxDynamicSharedMemorySize, SMEM_TOTAL);
    cudaFuncSetAttribute(k_burst_sk, cudaFuncAttributeMaxDynamicSharedMemorySize, SMEM_TOTAL);
    cudaFuncSetAttribute(k_agg,      cudaFuncAttributeMaxDynamicSharedMemorySize, SMEM_TOTAL);

    // 1: weight conversions + bias concat (x conversion fused into GEMM1)
    mega_convert<<<305, 256>>>(Wc1, Ws1, Wc2, Ws2, bc1, bs1);

    // 2: fused GEMM1 (in-flight x fp32->fp16) + token MLP layer 1
    k_gemm1<<<4096, 256, SMEM_TOTAL>>>(x, t, Wt1, bt1);

    // 3: GEMM2c + GEMM2s + token MLP layer 2
    k_gemm2<<<1536, 256, SMEM_TOTAL>>>(bc2, bs2, Wt2, bt2);

    // 4: fnt+colnorm + zero(bw) + Sinkhorn u1 (v==0)
    fnt2_kernel<<<1412, 256>>>(dust);

    // 5-8: burst Gram slices overlapped with Sinkhorn stages v1,u2,v2,u3
    //      (v3 fused into pfinal3). Wave-packed: 592=2.0w, 296=1.0w, 592=2.0w, 448=1.51w
    {
        int start = 0;
        k_burst_sk<<<128 + 464, 256, SMEM_TOTAL>>>(start, 128, 1, dust, ba, bbp); start += 464;
        k_burst_sk<<<260 + 36,  256, SMEM_TOTAL>>>(start, 260, 0, dust, ba, bbp); start += 36;
        k_burst_sk<<<128 + 464, 256, SMEM_TOTAL>>>(start, 128, 1, dust, ba, bbp); start += 464;
        k_burst_sk<<<260 + 188, 256, SMEM_TOTAL>>>(start, 260, 0, dust, ba, bbp);
    }

    // 9: transport plan with fused v3 (transposed, cterm folded)
    pfinal3_kernel<<<128, 256>>>(dust, bp);

    // 10-11: aggregation (split-K x4) + final normalize
    k_agg<<<128, 256, SMEM_TOTAL>>>();
    final_kernel<<<NB, 256>>>(out);
}